// round 9
// baseline (speedup 1.0000x reference)
#include <cuda_runtime.h>
#include <cuda_bf16.h>
#include <math.h>
#include <stdint.h>

#define BB 2
#define TT 2048
#define EE 768
#define HH 12
#define DH 64
#define VV 50257
#define NTOK (BB*TT)      // 4096
#define BH (BB*HH)        // 24
#define NQKV 2304         // 3*H*Dh
#define NPART 788         // 197 n-tiles * 4 warp-columns

// ---------------- scratch (device globals; no allocation allowed) ----------
__device__ float g_att[100663296];                   // 402 MB raw scores [bh][t][s]
__device__ float g_cinv[BH*TT];
__device__ float g_rowloss[NTOK];
__device__ float g_part[NTOK*NPART];                 // per-row expsum partials
__device__ __nv_bfloat16 g_hhi[NTOK*EE];             // embed hi/lo
__device__ __nv_bfloat16 g_hlo[NTOK*EE];
__device__ __nv_bfloat16 gWp_hi[NQKV*EE];            // packed QKV weights [n][e]
__device__ __nv_bfloat16 gWp_lo[NQKV*EE];
__device__ __nv_bfloat16 gq_hi[BH*TT*DH], gq_lo[BH*TT*DH];
__device__ __nv_bfloat16 gk_hi[BH*TT*DH], gk_lo[BH*TT*DH];
__device__ __nv_bfloat16 gvT_hi[BH*DH*TT], gvT_lo[BH*DH*TT];   // v transposed [bh][d][t]
__device__ __nv_bfloat16 gA_hi[NTOK*EE];             // attention out (A of logits GEMM)
__device__ __nv_bfloat16 gA_lo[NTOK*EE];
__device__ __nv_bfloat16 gW_hi[(size_t)VV*EE];       // Wout^T [V][E] K-major
__device__ __nv_bfloat16 gW_lo[(size_t)VV*EE];

// ---------------- PTX helpers ----------------------------------------------
__device__ __forceinline__ uint32_t smem_u32(const void* p) {
    uint32_t a;
    asm("{ .reg .u64 t; cvta.to.shared.u64 t, %1; cvt.u32.u64 %0, t; }" : "=r"(a) : "l"(p));
    return a;
}
__device__ __forceinline__ void cpasync16(uint32_t s, const void* g) {
    asm volatile("cp.async.cg.shared.global [%0], [%1], 16;" :: "r"(s), "l"(g));
}
#define CP_COMMIT() asm volatile("cp.async.commit_group;" ::: "memory")
#define CP_WAIT1()  asm volatile("cp.async.wait_group 1;" ::: "memory")
#define CP_WAIT0()  asm volatile("cp.async.wait_group 0;" ::: "memory")

#define LDSM_X4(r, addr) \
    asm volatile("ldmatrix.sync.aligned.m8n8.x4.shared.b16 {%0,%1,%2,%3}, [%4];" \
        : "=r"((r)[0]), "=r"((r)[1]), "=r"((r)[2]), "=r"((r)[3]) : "r"(addr))

#define MMA16816(c, a, b0, b1) \
    asm volatile("mma.sync.aligned.m16n8k16.row.col.f32.bf16.bf16.f32 " \
        "{%0,%1,%2,%3}, {%4,%5,%6,%7}, {%8,%9}, {%0,%1,%2,%3};" \
        : "+f"((c)[0]), "+f"((c)[1]), "+f"((c)[2]), "+f"((c)[3]) \
        : "r"((a)[0]), "r"((a)[1]), "r"((a)[2]), "r"((a)[3]), "r"(b0), "r"(b1))

__device__ __forceinline__ void split_bf16(float v, __nv_bfloat16& hi, __nv_bfloat16& lo) {
    hi = __float2bfloat16_rn(v);
    lo = __float2bfloat16_rn(v - __bfloat162float(hi));
}

// ---------------- K1: embed -> h hi/lo --------------------------------------
__global__ void k_embed(const int* __restrict__ x, const float* __restrict__ tok,
                        const float* __restrict__ pos) {
    int idx = blockIdx.x * 256 + threadIdx.x;
    int e  = idx % EE;
    int bt = idx / EE;
    int t  = bt % TT;
    float v = tok[(size_t)x[bt] * EE + e] + pos[t * EE + e];
    split_bf16(v, g_hhi[idx], g_hlo[idx]);
}

// ---------------- K2a: pack Wq/Wk/Wv -> [2304][768] bf16 hi/lo --------------
__global__ void k_packW(const float* __restrict__ Wq, const float* __restrict__ Wk,
                        const float* __restrict__ Wv) {
    int idx = blockIdx.x * 256 + threadIdx.x;       // over NQKV*EE
    int n = idx / EE, e = idx % EE;
    int mat = n / (HH * DH);
    int rem = n - mat * (HH * DH);
    int hh = rem >> 6, d = rem & 63;
    const float* W = (mat == 0 ? Wq : (mat == 1 ? Wk : Wv));
    float v = W[((size_t)hh * EE + e) * DH + d];
    split_bf16(v, gWp_hi[idx], gWp_lo[idx]);
}

// ---------------- K2b: transpose Wout [E][V] -> [V][E] bf16 hi/lo -----------
__global__ __launch_bounds__(256) void k_cvtW(const float* __restrict__ W) {
    __shared__ float tile[32][33];
    int n0 = blockIdx.x * 32;
    int k0 = blockIdx.y * 32;
    int tx = threadIdx.x, ty = threadIdx.y;   // 32 x 8
    #pragma unroll
    for (int j = 0; j < 4; j++) {
        int k = k0 + ty + j * 8;
        int n = n0 + tx;
        tile[ty + j * 8][tx] = (n < VV) ? W[(size_t)k * VV + n] : 0.f;
    }
    __syncthreads();
    #pragma unroll
    for (int j = 0; j < 4; j++) {
        int n = n0 + ty + j * 8;
        if (n < VV) {
            float v = tile[tx][ty + j * 8];
            size_t off = (size_t)n * EE + k0 + tx;
            split_bf16(v, gW_hi[off], gW_lo[off]);
        }
    }
}

// ---------------- K3: fused QKV projection (HMMA, hi/lo 3-pass) --------------
#define PSTAGE 32768
#define PSMEM  (2 * PSTAGE)
__global__ __launch_bounds__(256) void k_projmma() {
    extern __shared__ __align__(128) char smem[];
    const uint32_t sb = smem_u32(smem);
    const int tid = threadIdx.x;
    const int wid = tid >> 5, lane = tid & 31;
    const int m0 = blockIdx.x * 128;
    const int n0 = blockIdx.y * 128;
    const int wm0 = (wid & 1) * 64;
    const int wn0 = (wid >> 1) * 32;

    float acc[4][4][4];
    #pragma unroll
    for (int i = 0; i < 4; i++)
        #pragma unroll
        for (int j = 0; j < 4; j++)
            #pragma unroll
            for (int q = 0; q < 4; q++) acc[i][j][q] = 0.f;

    auto load_stage = [&](int p, int k0) {
        uint32_t base = sb + p * PSTAGE;
        int kbyte = k0 * 2;
        #pragma unroll
        for (int half = 0; half < 2; half++) {
            int j = tid + half * 256;
            int row = j >> 2, ch = j & 3;
            uint32_t soff = row * 64 + (((ch ^ (row & 3)) & 3) << 4);
            size_t ga = (size_t)(m0 + row) * (EE * 2) + kbyte + ch * 16;
            cpasync16(base + soff,         (const char*)g_hhi + ga);
            cpasync16(base + 8192 + soff,  (const char*)g_hlo + ga);
            size_t gb = (size_t)(n0 + row) * (EE * 2) + kbyte + ch * 16;
            cpasync16(base + 16384 + soff, (const char*)gWp_hi + gb);
            cpasync16(base + 24576 + soff, (const char*)gWp_lo + gb);
        }
    };

    load_stage(0, 0);
    CP_COMMIT();
    const int NIT = EE / 32;
    for (int it = 0; it < NIT; it++) {
        int p = it & 1;
        if (it + 1 < NIT) {
            load_stage(p ^ 1, (it + 1) * 32);
            CP_COMMIT();
            CP_WAIT1();
        } else {
            CP_WAIT0();
        }
        __syncthreads();
        uint32_t stage = sb + p * PSTAGE;
        #pragma unroll
        for (int kh = 0; kh < 2; kh++) {
            uint32_t aH[4][4], aL[4][4], bHf[2][4], bLf[2][4];
            #pragma unroll
            for (int mf = 0; mf < 4; mf++) {
                int row = wm0 + mf * 16 + (lane & 7) + ((lane >> 3) & 1) * 8;
                int ch = 2 * kh + (lane >> 4);
                uint32_t ad = stage + row * 64 + (((ch ^ (row & 3)) & 3) << 4);
                LDSM_X4(aH[mf], ad);
                LDSM_X4(aL[mf], ad + 8192);
            }
            #pragma unroll
            for (int g = 0; g < 2; g++) {
                int row = wn0 + g * 16 + (lane & 7) + ((lane >> 4) & 1) * 8;
                int ch = 2 * kh + ((lane >> 3) & 1);
                uint32_t ad = stage + 16384 + row * 64 + (((ch ^ (row & 3)) & 3) << 4);
                LDSM_X4(bHf[g], ad);
                LDSM_X4(bLf[g], ad + 8192);
            }
            #pragma unroll
            for (int mf = 0; mf < 4; mf++)
                #pragma unroll
                for (int g = 0; g < 2; g++)
                    #pragma unroll
                    for (int nh = 0; nh < 2; nh++) {
                        float* c = acc[mf][g * 2 + nh];
                        MMA16816(c, aH[mf], bHf[g][nh * 2], bHf[g][nh * 2 + 1]);
                        MMA16816(c, aH[mf], bLf[g][nh * 2], bLf[g][nh * 2 + 1]);
                        MMA16816(c, aL[mf], bHf[g][nh * 2], bHf[g][nh * 2 + 1]);
                    }
        }
        __syncthreads();
    }

    // epilogue: scatter to q/k hi/lo [bh][t][d] and v^T hi/lo [bh][d][t]
    const int mat = n0 / (HH * DH);     // tile never crosses a matrix boundary
    #pragma unroll
    for (int mf = 0; mf < 4; mf++) {
        int r0 = m0 + wm0 + mf * 16 + (lane >> 2);
        #pragma unroll
        for (int nf = 0; nf < 4; nf++) {
            float* a = acc[mf][nf];
            #pragma unroll
            for (int c2 = 0; c2 < 2; c2++) {
                int n = n0 + wn0 + nf * 8 + (lane & 3) * 2 + c2;
                int rem = n - mat * (HH * DH);
                int hh = rem >> 6, d = rem & 63;
                #pragma unroll
                for (int rr = 0; rr < 2; rr++) {
                    int r = r0 + rr * 8;
                    int b = r >> 11, t = r & 2047;
                    int bh = b * HH + hh;
                    float v = a[c2 + rr * 2];
                    __nv_bfloat16 hi, lo;
                    split_bf16(v, hi, lo);
                    if (mat == 0) {
                        size_t off = ((size_t)bh * TT + t) * DH + d;
                        gq_hi[off] = hi; gq_lo[off] = lo;
                    } else if (mat == 1) {
                        size_t off = ((size_t)bh * TT + t) * DH + d;
                        gk_hi[off] = hi; gk_lo[off] = lo;
                    } else {
                        size_t off = ((size_t)bh * DH + d) * TT + t;
                        gvT_hi[off] = hi; gvT_lo[off] = lo;
                    }
                }
            }
        }
    }
}

// ---------------- K4: scores via HMMA (128x128 tiles, K=64, 3-pass) ---------
#define SSMEM 65536
__global__ __launch_bounds__(256) void k_scores() {
    int zs = blockIdx.x, zt = blockIdx.y, bh = blockIdx.z;
    if (zs > zt) return;
    int s0 = zs * 128, t0 = zt * 128;
    extern __shared__ __align__(128) char smem[];
    const uint32_t sb = smem_u32(smem);
    const int tid = threadIdx.x;
    const int wid = tid >> 5, lane = tid & 31;
    const int wm0 = (wid & 1) * 64;
    const int wn0 = (wid >> 1) * 32;

    #pragma unroll
    for (int i = 0; i < 4; i++) {
        int j = tid + i * 256;                 // 0..1023
        int row = j >> 3, ch = j & 7;
        uint32_t soff = row * 128 + (((ch ^ (row & 7)) & 7) << 4);
        size_t gq = ((size_t)bh * TT + t0 + row) * 128 + ch * 16;
        size_t gk = ((size_t)bh * TT + s0 + row) * 128 + ch * 16;
        cpasync16(sb + soff,         (const char*)gq_hi + gq);
        cpasync16(sb + 16384 + soff, (const char*)gq_lo + gq);
        cpasync16(sb + 32768 + soff, (const char*)gk_hi + gk);
        cpasync16(sb + 49152 + soff, (const char*)gk_lo + gk);
    }
    CP_COMMIT();
    CP_WAIT0();
    __syncthreads();

    float acc[4][4][4];
    #pragma unroll
    for (int i = 0; i < 4; i++)
        #pragma unroll
        for (int j = 0; j < 4; j++)
            #pragma unroll
            for (int q = 0; q < 4; q++) acc[i][j][q] = 0.f;

    #pragma unroll
    for (int kh = 0; kh < 4; kh++) {
        uint32_t aH[4][4], aL[4][4], bHf[2][4], bLf[2][4];
        #pragma unroll
        for (int mf = 0; mf < 4; mf++) {
            int row = wm0 + mf * 16 + (lane & 7) + ((lane >> 3) & 1) * 8;
            int ch = 2 * kh + (lane >> 4);
            uint32_t ad = sb + row * 128 + (((ch ^ (row & 7)) & 7) << 4);
            LDSM_X4(aH[mf], ad);
            LDSM_X4(aL[mf], ad + 16384);
        }
        #pragma unroll
        for (int g = 0; g < 2; g++) {
            int row = wn0 + g * 16 + (lane & 7) + ((lane >> 4) & 1) * 8;
            int ch = 2 * kh + ((lane >> 3) & 1);
            uint32_t ad = sb + 32768 + row * 128 + (((ch ^ (row & 7)) & 7) << 4);
            LDSM_X4(bHf[g], ad);
            LDSM_X4(bLf[g], ad + 16384);
        }
        #pragma unroll
        for (int mf = 0; mf < 4; mf++)
            #pragma unroll
            for (int g = 0; g < 2; g++)
                #pragma unroll
                for (int nh = 0; nh < 2; nh++) {
                    float* c = acc[mf][g * 2 + nh];
                    MMA16816(c, aH[mf], bHf[g][nh * 2], bHf[g][nh * 2 + 1]);
                    MMA16816(c, aH[mf], bLf[g][nh * 2], bLf[g][nh * 2 + 1]);
                    MMA16816(c, aL[mf], bHf[g][nh * 2], bHf[g][nh * 2 + 1]);
                }
    }

    float* out = g_att + (size_t)bh * TT * TT;
    #pragma unroll
    for (int mf = 0; mf < 4; mf++) {
        int t = t0 + wm0 + mf * 16 + (lane >> 2);
        float* p0 = out + (size_t)t * TT;
        float* p1 = p0 + (size_t)8 * TT;
        #pragma unroll
        for (int nf = 0; nf < 4; nf++) {
            int s = s0 + wn0 + nf * 8 + (lane & 3) * 2;
            float* a = acc[mf][nf];
            p0[s]     = a[0] * 8.0f;
            p0[s + 1] = a[1] * 8.0f;
            p1[s]     = a[2] * 8.0f;
            p1[s + 1] = a[3] * 8.0f;
        }
    }
}

// ---------------- K5: per-column softmax sums (no max; scores tiny) ---------
__global__ void k_colstats() {
    int bh = blockIdx.y;
    int s0 = blockIdx.x * 256;
    int s = s0 + threadIdx.x;
    const float* base = g_att + (size_t)bh * TT * TT;
    float sum = 0.f;
    for (int t = s0; t < TT; ++t) {
        if (t >= s) sum += __expf(base[(size_t)t * TT + s]);
    }
    g_cinv[bh * TT + s] = 1.0f / sum;
}

// ---------------- K6: o = softmax(att) @ v via HMMA -------------------------
#define ASMEM 49152
__global__ __launch_bounds__(256) void k_av() {
    int zt = blockIdx.x, bh = blockIdx.y;
    int t0 = zt * 128;
    int b = bh / HH, h = bh % HH;
    extern __shared__ __align__(128) char smem[];
    const uint32_t sb = smem_u32(smem);
    __nv_bfloat16* whi = (__nv_bfloat16*)smem;
    __nv_bfloat16* wlo = (__nv_bfloat16*)(smem + 16384);
    const int tid = threadIdx.x;
    const int wid = tid >> 5, lane = tid & 31;
    const int wm0 = (wid & 3) * 32;
    const int wn0 = (wid >> 2) * 32;

    const float* att = g_att + (size_t)bh * TT * TT;
    const float* ci  = g_cinv + bh * TT;

    float acc[2][4][4];
    #pragma unroll
    for (int i = 0; i < 2; i++)
        #pragma unroll
        for (int j = 0; j < 4; j++)
            #pragma unroll
            for (int q = 0; q < 4; q++) acc[i][j][q] = 0.f;

    int nchunks = 2 * zt + 2;
    for (int c = 0; c < nchunks; c++) {
        int s0 = c * 64;
        #pragma unroll
        for (int i = 0; i < 2; i++) {
            int j = tid + i * 256;             // 0..511
            int row = j >> 3, ch = j & 7;
            uint32_t soff = row * 128 + (((ch ^ (row & 7)) & 7) << 4);
            size_t gv = ((size_t)bh * DH + row) * (TT * 2) + s0 * 2 + ch * 16;
            cpasync16(sb + 32768 + soff, (const char*)gvT_hi + gv);
            cpasync16(sb + 40960 + soff, (const char*)gvT_lo + gv);
        }
        CP_COMMIT();
        #pragma unroll
        for (int i = 0; i < 32; i++) {
            int j = tid + i * 256;             // 0..8191
            int row = j >> 6, sc = j & 63;
            int t = t0 + row, s = s0 + sc;
            float w = 0.f;
            if (s <= t) {
                w = __expf(att[(size_t)t * TT + s]) * ci[s];
            }
            __nv_bfloat16 hi, lo;
            split_bf16(w, hi, lo);
            int ch = sc >> 3;
            uint32_t soff = row * 128 + (((ch ^ (row & 7)) & 7) << 4) + (sc & 7) * 2;
            *(__nv_bfloat16*)((char*)whi + soff) = hi;
            *(__nv_bfloat16*)((char*)wlo + soff) = lo;
        }
        CP_WAIT0();
        __syncthreads();

        #pragma unroll
        for (int kh = 0; kh < 4; kh++) {
            uint32_t aH[2][4], aL[2][4], bHf[2][4], bLf[2][4];
            #pragma unroll
            for (int mf = 0; mf < 2; mf++) {
                int row = wm0 + mf * 16 + (lane & 7) + ((lane >> 3) & 1) * 8;
                int ch = 2 * kh + (lane >> 4);
                uint32_t ad = sb + row * 128 + (((ch ^ (row & 7)) & 7) << 4);
                LDSM_X4(aH[mf], ad);
                LDSM_X4(aL[mf], ad + 16384);
            }
            #pragma unroll
            for (int g = 0; g < 2; g++) {
                int row = wn0 + g * 16 + (lane & 7) + ((lane >> 4) & 1) * 8;
                int ch = 2 * kh + ((lane >> 3) & 1);
                uint32_t ad = sb + 32768 + row * 128 + (((ch ^ (row & 7)) & 7) << 4);
                LDSM_X4(bHf[g], ad);
                LDSM_X4(bLf[g], ad + 8192);
            }
            #pragma unroll
            for (int mf = 0; mf < 2; mf++)
                #pragma unroll
                for (int g = 0; g < 2; g++)
                    #pragma unroll
                    for (int nh = 0; nh < 2; nh++) {
                        float* cc = acc[mf][g * 2 + nh];
                        MMA16816(cc, aH[mf], bHf[g][nh * 2], bHf[g][nh * 2 + 1]);
                        MMA16816(cc, aH[mf], bLf[g][nh * 2], bLf[g][nh * 2 + 1]);
                        MMA16816(cc, aL[mf], bHf[g][nh * 2], bHf[g][nh * 2 + 1]);
                    }
        }
        __syncthreads();
    }

    #pragma unroll
    for (int mf = 0; mf < 2; mf++) {
        int t = t0 + wm0 + mf * 16 + (lane >> 2);
        #pragma unroll
        for (int nf = 0; nf < 4; nf++) {
            int d = wn0 + nf * 8 + (lane & 3) * 2;
            float* a = acc[mf][nf];
            #pragma unroll
            for (int rr = 0; rr < 2; rr++) {
                int tt = t + rr * 8;
                size_t off = ((size_t)b * TT + tt) * EE + h * DH + d;
                __nv_bfloat16 hi, lo;
                split_bf16(a[rr * 2], hi, lo);
                gA_hi[off] = hi; gA_lo[off] = lo;
                split_bf16(a[rr * 2 + 1], hi, lo);
                gA_hi[off + 1] = hi; gA_lo[off + 1] = lo;
            }
        }
    }
}

// ---------------- K7: logits GEMM (HMMA, 128x256 tile, 64x64 warps) ---------
// 3-stage cp.async; epilogue writes logits AND per-row expsum partials.
#define GSTAGE 49152                 // Ahi 8K, Alo 8K, Bhi 16K, Blo 16K
#define GSMEM_BYTES (3 * GSTAGE)     // 144 KB
__global__ __launch_bounds__(256) void k_gemm(const float* __restrict__ bias,
                                              float* __restrict__ C) {
    extern __shared__ __align__(128) char smem[];
    const uint32_t sb = smem_u32(smem);
    const int tid = threadIdx.x;
    const int wid = tid >> 5, lane = tid & 31;
    const int m0 = blockIdx.x * 128;
    const int n0 = blockIdx.y * 256;
    const int wm0 = (wid & 1) * 64;      // warp covers 64 rows
    const int wn0 = (wid >> 1) * 64;     // warp covers 64 cols

    float acc[4][8][4];
    #pragma unroll
    for (int i = 0; i < 4; i++)
        #pragma unroll
        for (int j = 0; j < 8; j++)
            #pragma unroll
            for (int q = 0; q < 4; q++) acc[i][j][q] = 0.f;

    auto load_stage = [&](int p, int k0) {
        uint32_t base = sb + p * GSTAGE;
        int kbyte = k0 * 2;
        // A: 128 rows x 64B (hi+lo), 512 chunks -> 2 per thread
        #pragma unroll
        for (int half = 0; half < 2; half++) {
            int j = tid + half * 256;
            int row = j >> 2, ch = j & 3;
            uint32_t soff = row * 64 + (((ch ^ (row & 3)) & 3) << 4);
            size_t ga = (size_t)(m0 + row) * (EE * 2) + kbyte + ch * 16;
            cpasync16(base + soff,        (const char*)gA_hi + ga);
            cpasync16(base + 8192 + soff, (const char*)gA_lo + ga);
        }
        // B: 256 rows x 64B (hi+lo), 1024 chunks -> 4 per thread
        #pragma unroll
        for (int q4 = 0; q4 < 4; q4++) {
            int j = tid + q4 * 256;
            int row = j >> 2, ch = j & 3;
            uint32_t soff = row * 64 + (((ch ^ (row & 3)) & 3) << 4);
            int nn = n0 + row; if (nn >= VV) nn = VV - 1;
            size_t gb = (size_t)nn * (EE * 2) + kbyte + ch * 16;
            cpasync16(base + 16384 + soff, (const char*)gW_hi + gb);
            cpasync16(base + 32768 + soff, (const char*)gW_lo + gb);
        }
    };

    load_stage(0, 0);
    CP_COMMIT();
    load_stage(1, 32);
    CP_COMMIT();

    const int NIT = EE / 32;    // 24
    int buf = 0;
    for (int it = 0; it < NIT; it++) {
        if (it + 1 < NIT) { CP_WAIT1(); } else { CP_WAIT0(); }
        __syncthreads();
        if (it + 2 < NIT) {
            int nb = buf + 2; if (nb >= 3) nb -= 3;
            load_stage(nb, (it + 2) * 32);
            CP_COMMIT();
        }
        uint32_t stage = sb + buf * GSTAGE;
        #pragma unroll
        for (int kh = 0; kh < 2; kh++) {
            uint32_t aH[4][4], aL[4][4], bHf[4][4], bLf[4][4];
            #pragma unroll
            for (int mf = 0; mf < 4; mf++) {
                int row = wm0 + mf * 16 + (lane & 7) + ((lane >> 3) & 1) * 8;
                int ch = 2 * kh + (lane >> 4);
                uint32_t ad = stage + row * 64 + (((ch ^ (row & 3)) & 3) << 4);
                LDSM_X4(aH[mf], ad);
                LDSM_X4(aL[mf], ad + 8192);
            }
            #pragma unroll
            for (int g = 0; g < 4; g++) {
                int row = wn0 + g * 16 + (lane & 7) + ((lane >> 4) & 1) * 8;
                int ch = 2 * kh + ((lane >> 3) & 1);
                uint32_t ad = stage + 16384 + row * 64 + (((ch ^ (row & 3)) & 3) << 4);
                LDSM_X4(bHf[g], ad);
                LDSM_X4(bLf[g], ad + 16384);
            }
            #pragma unroll
            for (int mf = 0; mf < 4; mf++)
                #pragma unroll
                for (int g = 0; g < 4; g++)
                    #pragma unroll
                    for (int nh = 0; nh < 2; nh++) {
                        float* c = acc[mf][g * 2 + nh];
                        MMA16816(c, aH[mf], bHf[g][nh * 2], bHf[g][nh * 2 + 1]);
                        MMA16816(c, aH[mf], bLf[g][nh * 2], bLf[g][nh * 2 + 1]);
                        MMA16816(c, aL[mf], bHf[g][nh * 2], bHf[g][nh * 2 + 1]);
                    }
        }
        buf++; if (buf == 3) buf = 0;
    }

    // epilogue: write logits + per-row expsum partials (deterministic slots)
    const int py = blockIdx.y * 4 + (wid >> 1);
    #pragma unroll
    for (int mf = 0; mf < 4; mf++) {
        int r = m0 + wm0 + mf * 16 + (lane >> 2);
        float* p0 = C + (size_t)r * VV;
        float* p1 = p0 + (size_t)8 * VV;
        float e0 = 0.f, e1 = 0.f;
        #pragma unroll
        for (int nf = 0; nf < 8; nf++) {
            int cc = n0 + wn0 + nf * 8 + (lane & 3) * 2;
            float* a = acc[mf][nf];
            if (cc < VV) {
                float bv = __ldg(&bias[cc]);
                float v0 = a[0] + bv, v2 = a[2] + bv;
                p0[cc] = v0; p1[cc] = v2;
                e0 += __expf(v0); e1 += __expf(v2);
            }
            if (cc + 1 < VV) {
                float bv = __ldg(&bias[cc + 1]);
                float v1 = a[1] + bv, v3 = a[3] + bv;
                p0[cc + 1] = v1; p1[cc + 1] = v3;
                e0 += __expf(v1); e1 += __expf(v3);
            }
        }
        // reduce across the 4 lanes sharing each row
        e0 += __shfl_xor_sync(0xffffffffu, e0, 1);
        e0 += __shfl_xor_sync(0xffffffffu, e0, 2);
        e1 += __shfl_xor_sync(0xffffffffu, e1, 1);
        e1 += __shfl_xor_sync(0xffffffffu, e1, 2);
        if ((lane & 3) == 0) {
            g_part[(size_t)r * NPART + py]       = e0;
            g_part[(size_t)(r + 8) * NPART + py] = e1;
        }
    }
}

// ---------------- K8: per-row lse from partials + target gather -------------
__global__ __launch_bounds__(256) void k_rowloss(const float* __restrict__ logits,
                                                 const int* __restrict__ y) {
    int row = blockIdx.x;
    int tid = threadIdx.x;
    float s = 0.f;
    for (int i = tid; i < NPART; i += 256) s += g_part[(size_t)row * NPART + i];
    __shared__ float ss[256];
    ss[tid] = s;
    __syncthreads();
    for (int off = 128; off > 0; off >>= 1) {
        if (tid < off) ss[tid] += ss[tid + off];
        __syncthreads();
    }
    if (tid == 0) {
        g_rowloss[row] = logf(ss[0]) - logits[(size_t)row * VV + y[row]];
    }
}

// ---------------- K9: mean -> loss scalar -----------------------------------
__global__ void k_loss(float* __restrict__ out) {
    __shared__ float sb[256];
    int tid = threadIdx.x;
    float s = 0.f;
    for (int i = tid; i < NTOK; i += 256) s += g_rowloss[i];
    sb[tid] = s;
    __syncthreads();
    for (int off = 128; off > 0; off >>= 1) {
        if (tid < off) sb[tid] += sb[tid + off];
        __syncthreads();
    }
    if (tid == 0) out[0] = sb[0] / (float)NTOK;
}

// ---------------- launch -----------------------------------------------------
extern "C" void kernel_launch(void* const* d_in, const int* in_sizes, int n_in,
                              void* d_out, int out_size) {
    const int*   x    = (const int*)d_in[0];
    const int*   y    = (const int*)d_in[1];
    const float* tok  = (const float*)d_in[2];
    const float* pos  = (const float*)d_in[3];
    const float* Wq   = (const float*)d_in[4];
    const float* Wk   = (const float*)d_in[5];
    const float* Wv   = (const float*)d_in[6];
    const float* Wout = (const float*)d_in[7];
    const float* bout = (const float*)d_in[8];
    float* out = (float*)d_out;

    cudaFuncSetAttribute(k_projmma, cudaFuncAttributeMaxDynamicSharedMemorySize, PSMEM);
    cudaFuncSetAttribute(k_scores,  cudaFuncAttributeMaxDynamicSharedMemorySize, SSMEM);
    cudaFuncSetAttribute(k_av,      cudaFuncAttributeMaxDynamicSharedMemorySize, ASMEM);
    cudaFuncSetAttribute(k_gemm,    cudaFuncAttributeMaxDynamicSharedMemorySize, GSMEM_BYTES);

    k_embed<<<NTOK * EE / 256, 256>>>(x, tok, pos);
    k_packW<<<NQKV * EE / 256, 256>>>(Wq, Wk, Wv);
    k_cvtW<<<dim3((VV + 31) / 32, EE / 32), dim3(32, 8)>>>(Wout);

    k_projmma<<<dim3(NTOK / 128, NQKV / 128), 256, PSMEM>>>();

    k_scores<<<dim3(16, 16, BH), 256, SSMEM>>>();

    k_colstats<<<dim3(TT / 256, BH), 256>>>();

    k_av<<<dim3(TT / 128, BH), 256, ASMEM>>>();

    k_gemm<<<dim3(NTOK / 128, (VV + 255) / 256), 256, GSMEM_BYTES>>>(bout, out);

    k_rowloss<<<NTOK, 256>>>(out, y);

    long long nlogits = (long long)NTOK * VV;
    if ((long long)out_size > nlogits) {
        k_loss<<<1, 256>>>(out + nlogits);
    }
}

// round 11
// speedup vs baseline: 1.1177x; 1.1177x over previous
#include <cuda_runtime.h>
#include <cuda_bf16.h>
#include <math.h>
#include <stdint.h>

#define BB 2
#define TT 2048
#define EE 768
#define HH 12
#define DH 64
#define VV 50257
#define NTOK (BB*TT)      // 4096
#define BH (BB*HH)        // 24
#define NQKV 2304         // 3*H*Dh
#define NPART 1572        // 393 n-tiles * 4 warp-columns

// ---------------- scratch (device globals; no allocation allowed) ----------
__device__ float g_att[100663296];                   // 402 MB raw scores [bh][t][s]
__device__ float g_cinv[BH*TT];
__device__ float g_rowloss[NTOK];
__device__ float g_part[(size_t)NTOK*NPART];         // per-row expsum partials
__device__ __nv_bfloat16 g_hhi[NTOK*EE];             // embed hi/lo
__device__ __nv_bfloat16 g_hlo[NTOK*EE];
__device__ __nv_bfloat16 gWp_hi[NQKV*EE];            // packed QKV weights [n][e]
__device__ __nv_bfloat16 gWp_lo[NQKV*EE];
__device__ __nv_bfloat16 gq_hi[BH*TT*DH], gq_lo[BH*TT*DH];
__device__ __nv_bfloat16 gk_hi[BH*TT*DH], gk_lo[BH*TT*DH];
__device__ __nv_bfloat16 gvT_hi[BH*DH*TT], gvT_lo[BH*DH*TT];   // v transposed [bh][d][t]
__device__ __nv_bfloat16 gA_hi[NTOK*EE];             // attention out (A of logits GEMM)
__device__ __nv_bfloat16 gA_lo[NTOK*EE];
__device__ __nv_bfloat16 gW_hi[(size_t)VV*EE];       // Wout^T [V][E] K-major
__device__ __nv_bfloat16 gW_lo[(size_t)VV*EE];

// ---------------- PTX helpers ----------------------------------------------
__device__ __forceinline__ uint32_t smem_u32(const void* p) {
    uint32_t a;
    asm("{ .reg .u64 t; cvta.to.shared.u64 t, %1; cvt.u32.u64 %0, t; }" : "=r"(a) : "l"(p));
    return a;
}
__device__ __forceinline__ void cpasync16(uint32_t s, const void* g) {
    asm volatile("cp.async.cg.shared.global [%0], [%1], 16;" :: "r"(s), "l"(g));
}
#define CP_COMMIT() asm volatile("cp.async.commit_group;" ::: "memory")
#define CP_WAIT1()  asm volatile("cp.async.wait_group 1;" ::: "memory")
#define CP_WAIT0()  asm volatile("cp.async.wait_group 0;" ::: "memory")

#define LDSM_X4(r, addr) \
    asm volatile("ldmatrix.sync.aligned.m8n8.x4.shared.b16 {%0,%1,%2,%3}, [%4];" \
        : "=r"((r)[0]), "=r"((r)[1]), "=r"((r)[2]), "=r"((r)[3]) : "r"(addr))

#define MMA16816(c, a, b0, b1) \
    asm volatile("mma.sync.aligned.m16n8k16.row.col.f32.bf16.bf16.f32 " \
        "{%0,%1,%2,%3}, {%4,%5,%6,%7}, {%8,%9}, {%0,%1,%2,%3};" \
        : "+f"((c)[0]), "+f"((c)[1]), "+f"((c)[2]), "+f"((c)[3]) \
        : "r"((a)[0]), "r"((a)[1]), "r"((a)[2]), "r"((a)[3]), "r"(b0), "r"(b1))

__device__ __forceinline__ void split_bf16(float v, __nv_bfloat16& hi, __nv_bfloat16& lo) {
    hi = __float2bfloat16_rn(v);
    lo = __float2bfloat16_rn(v - __bfloat162float(hi));
}

// ---------------- K1: embed -> h hi/lo --------------------------------------
__global__ void k_embed(const int* __restrict__ x, const float* __restrict__ tok,
                        const float* __restrict__ pos) {
    int idx = blockIdx.x * 256 + threadIdx.x;
    int e  = idx % EE;
    int bt = idx / EE;
    int t  = bt % TT;
    float v = tok[(size_t)x[bt] * EE + e] + pos[t * EE + e];
    split_bf16(v, g_hhi[idx], g_hlo[idx]);
}

// ---------------- K2a: pack Wq/Wk/Wv -> [2304][768] bf16 hi/lo --------------
__global__ void k_packW(const float* __restrict__ Wq, const float* __restrict__ Wk,
                        const float* __restrict__ Wv) {
    int idx = blockIdx.x * 256 + threadIdx.x;       // over NQKV*EE
    int n = idx / EE, e = idx % EE;
    int mat = n / (HH * DH);
    int rem = n - mat * (HH * DH);
    int hh = rem >> 6, d = rem & 63;
    const float* W = (mat == 0 ? Wq : (mat == 1 ? Wk : Wv));
    float v = W[((size_t)hh * EE + e) * DH + d];
    split_bf16(v, gWp_hi[idx], gWp_lo[idx]);
}

// ---------------- K2b: transpose Wout [E][V] -> [V][E] bf16 hi/lo -----------
__global__ __launch_bounds__(256) void k_cvtW(const float* __restrict__ W) {
    __shared__ float tile[32][33];
    int n0 = blockIdx.x * 32;
    int k0 = blockIdx.y * 32;
    int tx = threadIdx.x, ty = threadIdx.y;   // 32 x 8
    #pragma unroll
    for (int j = 0; j < 4; j++) {
        int k = k0 + ty + j * 8;
        int n = n0 + tx;
        tile[ty + j * 8][tx] = (n < VV) ? W[(size_t)k * VV + n] : 0.f;
    }
    __syncthreads();
    #pragma unroll
    for (int j = 0; j < 4; j++) {
        int n = n0 + ty + j * 8;
        if (n < VV) {
            float v = tile[tx][ty + j * 8];
            size_t off = (size_t)n * EE + k0 + tx;
            split_bf16(v, gW_hi[off], gW_lo[off]);
        }
    }
}

// ---------------- K3: fused QKV projection (HMMA, hi/lo 3-pass) --------------
#define PSTAGE 32768
#define PSMEM  (2 * PSTAGE)
__global__ __launch_bounds__(256) void k_projmma() {
    extern __shared__ __align__(128) char smem[];
    const uint32_t sb = smem_u32(smem);
    const int tid = threadIdx.x;
    const int wid = tid >> 5, lane = tid & 31;
    const int m0 = blockIdx.x * 128;
    const int n0 = blockIdx.y * 128;
    const int wm0 = (wid & 1) * 64;
    const int wn0 = (wid >> 1) * 32;

    float acc[4][4][4];
    #pragma unroll
    for (int i = 0; i < 4; i++)
        #pragma unroll
        for (int j = 0; j < 4; j++)
            #pragma unroll
            for (int q = 0; q < 4; q++) acc[i][j][q] = 0.f;

    auto load_stage = [&](int p, int k0) {
        uint32_t base = sb + p * PSTAGE;
        int kbyte = k0 * 2;
        #pragma unroll
        for (int half = 0; half < 2; half++) {
            int j = tid + half * 256;
            int row = j >> 2, ch = j & 3;
            uint32_t soff = row * 64 + (((ch ^ (row & 3)) & 3) << 4);
            size_t ga = (size_t)(m0 + row) * (EE * 2) + kbyte + ch * 16;
            cpasync16(base + soff,         (const char*)g_hhi + ga);
            cpasync16(base + 8192 + soff,  (const char*)g_hlo + ga);
            size_t gb = (size_t)(n0 + row) * (EE * 2) + kbyte + ch * 16;
            cpasync16(base + 16384 + soff, (const char*)gWp_hi + gb);
            cpasync16(base + 24576 + soff, (const char*)gWp_lo + gb);
        }
    };

    load_stage(0, 0);
    CP_COMMIT();
    const int NIT = EE / 32;
    for (int it = 0; it < NIT; it++) {
        int p = it & 1;
        if (it + 1 < NIT) {
            load_stage(p ^ 1, (it + 1) * 32);
            CP_COMMIT();
            CP_WAIT1();
        } else {
            CP_WAIT0();
        }
        __syncthreads();
        uint32_t stage = sb + p * PSTAGE;
        #pragma unroll
        for (int kh = 0; kh < 2; kh++) {
            uint32_t aH[4][4], aL[4][4], bHf[2][4], bLf[2][4];
            #pragma unroll
            for (int mf = 0; mf < 4; mf++) {
                int row = wm0 + mf * 16 + (lane & 7) + ((lane >> 3) & 1) * 8;
                int ch = 2 * kh + (lane >> 4);
                uint32_t ad = stage + row * 64 + (((ch ^ (row & 3)) & 3) << 4);
                LDSM_X4(aH[mf], ad);
                LDSM_X4(aL[mf], ad + 8192);
            }
            #pragma unroll
            for (int g = 0; g < 2; g++) {
                int row = wn0 + g * 16 + (lane & 7) + ((lane >> 4) & 1) * 8;
                int ch = 2 * kh + ((lane >> 3) & 1);
                uint32_t ad = stage + 16384 + row * 64 + (((ch ^ (row & 3)) & 3) << 4);
                LDSM_X4(bHf[g], ad);
                LDSM_X4(bLf[g], ad + 8192);
            }
            #pragma unroll
            for (int mf = 0; mf < 4; mf++)
                #pragma unroll
                for (int g = 0; g < 2; g++)
                    #pragma unroll
                    for (int nh = 0; nh < 2; nh++) {
                        float* c = acc[mf][g * 2 + nh];
                        MMA16816(c, aH[mf], bHf[g][nh * 2], bHf[g][nh * 2 + 1]);
                        MMA16816(c, aH[mf], bLf[g][nh * 2], bLf[g][nh * 2 + 1]);
                        MMA16816(c, aL[mf], bHf[g][nh * 2], bHf[g][nh * 2 + 1]);
                    }
        }
        __syncthreads();
    }

    // epilogue: scatter to q/k hi/lo [bh][t][d] and v^T hi/lo [bh][d][t]
    const int mat = n0 / (HH * DH);     // tile never crosses a matrix boundary
    #pragma unroll
    for (int mf = 0; mf < 4; mf++) {
        int r0 = m0 + wm0 + mf * 16 + (lane >> 2);
        #pragma unroll
        for (int nf = 0; nf < 4; nf++) {
            float* a = acc[mf][nf];
            #pragma unroll
            for (int c2 = 0; c2 < 2; c2++) {
                int n = n0 + wn0 + nf * 8 + (lane & 3) * 2 + c2;
                int rem = n - mat * (HH * DH);
                int hh = rem >> 6, d = rem & 63;
                #pragma unroll
                for (int rr = 0; rr < 2; rr++) {
                    int r = r0 + rr * 8;
                    int b = r >> 11, t = r & 2047;
                    int bh = b * HH + hh;
                    float v = a[c2 + rr * 2];
                    __nv_bfloat16 hi, lo;
                    split_bf16(v, hi, lo);
                    if (mat == 0) {
                        size_t off = ((size_t)bh * TT + t) * DH + d;
                        gq_hi[off] = hi; gq_lo[off] = lo;
                    } else if (mat == 1) {
                        size_t off = ((size_t)bh * TT + t) * DH + d;
                        gk_hi[off] = hi; gk_lo[off] = lo;
                    } else {
                        size_t off = ((size_t)bh * DH + d) * TT + t;
                        gvT_hi[off] = hi; gvT_lo[off] = lo;
                    }
                }
            }
        }
    }
}

// ---------------- K4: scores via HMMA (128x128 tiles, K=64, 3-pass) ---------
#define SSMEM 65536
__global__ __launch_bounds__(256) void k_scores() {
    int zs = blockIdx.x, zt = blockIdx.y, bh = blockIdx.z;
    if (zs > zt) return;
    int s0 = zs * 128, t0 = zt * 128;
    extern __shared__ __align__(128) char smem[];
    const uint32_t sb = smem_u32(smem);
    const int tid = threadIdx.x;
    const int wid = tid >> 5, lane = tid & 31;
    const int wm0 = (wid & 1) * 64;
    const int wn0 = (wid >> 1) * 32;

    #pragma unroll
    for (int i = 0; i < 4; i++) {
        int j = tid + i * 256;                 // 0..1023
        int row = j >> 3, ch = j & 7;
        uint32_t soff = row * 128 + (((ch ^ (row & 7)) & 7) << 4);
        size_t gq = ((size_t)bh * TT + t0 + row) * 128 + ch * 16;
        size_t gk = ((size_t)bh * TT + s0 + row) * 128 + ch * 16;
        cpasync16(sb + soff,         (const char*)gq_hi + gq);
        cpasync16(sb + 16384 + soff, (const char*)gq_lo + gq);
        cpasync16(sb + 32768 + soff, (const char*)gk_hi + gk);
        cpasync16(sb + 49152 + soff, (const char*)gk_lo + gk);
    }
    CP_COMMIT();
    CP_WAIT0();
    __syncthreads();

    float acc[4][4][4];
    #pragma unroll
    for (int i = 0; i < 4; i++)
        #pragma unroll
        for (int j = 0; j < 4; j++)
            #pragma unroll
            for (int q = 0; q < 4; q++) acc[i][j][q] = 0.f;

    #pragma unroll
    for (int kh = 0; kh < 4; kh++) {
        uint32_t aH[4][4], aL[4][4], bHf[2][4], bLf[2][4];
        #pragma unroll
        for (int mf = 0; mf < 4; mf++) {
            int row = wm0 + mf * 16 + (lane & 7) + ((lane >> 3) & 1) * 8;
            int ch = 2 * kh + (lane >> 4);
            uint32_t ad = sb + row * 128 + (((ch ^ (row & 7)) & 7) << 4);
            LDSM_X4(aH[mf], ad);
            LDSM_X4(aL[mf], ad + 16384);
        }
        #pragma unroll
        for (int g = 0; g < 2; g++) {
            int row = wn0 + g * 16 + (lane & 7) + ((lane >> 4) & 1) * 8;
            int ch = 2 * kh + ((lane >> 3) & 1);
            uint32_t ad = sb + 32768 + row * 128 + (((ch ^ (row & 7)) & 7) << 4);
            LDSM_X4(bHf[g], ad);
            LDSM_X4(bLf[g], ad + 16384);
        }
        #pragma unroll
        for (int mf = 0; mf < 4; mf++)
            #pragma unroll
            for (int g = 0; g < 2; g++)
                #pragma unroll
                for (int nh = 0; nh < 2; nh++) {
                    float* c = acc[mf][g * 2 + nh];
                    MMA16816(c, aH[mf], bHf[g][nh * 2], bHf[g][nh * 2 + 1]);
                    MMA16816(c, aH[mf], bLf[g][nh * 2], bLf[g][nh * 2 + 1]);
                    MMA16816(c, aL[mf], bHf[g][nh * 2], bHf[g][nh * 2 + 1]);
                }
    }

    float* out = g_att + (size_t)bh * TT * TT;
    #pragma unroll
    for (int mf = 0; mf < 4; mf++) {
        int t = t0 + wm0 + mf * 16 + (lane >> 2);
        float* p0 = out + (size_t)t * TT;
        float* p1 = p0 + (size_t)8 * TT;
        #pragma unroll
        for (int nf = 0; nf < 4; nf++) {
            int s = s0 + wn0 + nf * 8 + (lane & 3) * 2;
            float* a = acc[mf][nf];
            *(float2*)(p0 + s) = make_float2(a[0] * 8.0f, a[1] * 8.0f);
            *(float2*)(p1 + s) = make_float2(a[2] * 8.0f, a[3] * 8.0f);
        }
    }
}

// ---------------- K5: per-column softmax sums (no max; scores tiny) ---------
__global__ void k_colstats() {
    int bh = blockIdx.y;
    int s0 = blockIdx.x * 256;
    int s = s0 + threadIdx.x;
    const float* base = g_att + (size_t)bh * TT * TT;
    float sum = 0.f;
    for (int t = s0; t < TT; ++t) {
        if (t >= s) sum += __expf(base[(size_t)t * TT + s]);
    }
    g_cinv[bh * TT + s] = 1.0f / sum;
}

// ---------------- K6: o = softmax(att) @ v via HMMA -------------------------
#define ASMEM 49152
__global__ __launch_bounds__(256) void k_av() {
    int zt = blockIdx.x, bh = blockIdx.y;
    int t0 = zt * 128;
    int b = bh / HH, h = bh % HH;
    extern __shared__ __align__(128) char smem[];
    const uint32_t sb = smem_u32(smem);
    __nv_bfloat16* whi = (__nv_bfloat16*)smem;
    __nv_bfloat16* wlo = (__nv_bfloat16*)(smem + 16384);
    const int tid = threadIdx.x;
    const int wid = tid >> 5, lane = tid & 31;
    const int wm0 = (wid & 3) * 32;
    const int wn0 = (wid >> 2) * 32;

    const float* att = g_att + (size_t)bh * TT * TT;
    const float* ci  = g_cinv + bh * TT;

    float acc[2][4][4];
    #pragma unroll
    for (int i = 0; i < 2; i++)
        #pragma unroll
        for (int j = 0; j < 4; j++)
            #pragma unroll
            for (int q = 0; q < 4; q++) acc[i][j][q] = 0.f;

    int nchunks = 2 * zt + 2;
    for (int c = 0; c < nchunks; c++) {
        int s0 = c * 64;
        #pragma unroll
        for (int i = 0; i < 2; i++) {
            int j = tid + i * 256;             // 0..511
            int row = j >> 3, ch = j & 7;
            uint32_t soff = row * 128 + (((ch ^ (row & 7)) & 7) << 4);
            size_t gv = ((size_t)bh * DH + row) * (TT * 2) + s0 * 2 + ch * 16;
            cpasync16(sb + 32768 + soff, (const char*)gvT_hi + gv);
            cpasync16(sb + 40960 + soff, (const char*)gvT_lo + gv);
        }
        CP_COMMIT();
        #pragma unroll
        for (int i = 0; i < 32; i++) {
            int j = tid + i * 256;             // 0..8191
            int row = j >> 6, sc = j & 63;
            int t = t0 + row, s = s0 + sc;
            float w = 0.f;
            if (s <= t) {
                w = __expf(att[(size_t)t * TT + s]) * ci[s];
            }
            __nv_bfloat16 hi, lo;
            split_bf16(w, hi, lo);
            int ch = sc >> 3;
            uint32_t soff = row * 128 + (((ch ^ (row & 7)) & 7) << 4) + (sc & 7) * 2;
            *(__nv_bfloat16*)((char*)whi + soff) = hi;
            *(__nv_bfloat16*)((char*)wlo + soff) = lo;
        }
        CP_WAIT0();
        __syncthreads();

        #pragma unroll
        for (int kh = 0; kh < 4; kh++) {
            uint32_t aH[2][4], aL[2][4], bHf[2][4], bLf[2][4];
            #pragma unroll
            for (int mf = 0; mf < 2; mf++) {
                int row = wm0 + mf * 16 + (lane & 7) + ((lane >> 3) & 1) * 8;
                int ch = 2 * kh + (lane >> 4);
                uint32_t ad = sb + row * 128 + (((ch ^ (row & 7)) & 7) << 4);
                LDSM_X4(aH[mf], ad);
                LDSM_X4(aL[mf], ad + 16384);
            }
            #pragma unroll
            for (int g = 0; g < 2; g++) {
                int row = wn0 + g * 16 + (lane & 7) + ((lane >> 4) & 1) * 8;
                int ch = 2 * kh + ((lane >> 3) & 1);
                uint32_t ad = sb + 32768 + row * 128 + (((ch ^ (row & 7)) & 7) << 4);
                LDSM_X4(bHf[g], ad);
                LDSM_X4(bLf[g], ad + 8192);
            }
            #pragma unroll
            for (int mf = 0; mf < 2; mf++)
                #pragma unroll
                for (int g = 0; g < 2; g++)
                    #pragma unroll
                    for (int nh = 0; nh < 2; nh++) {
                        float* cc = acc[mf][g * 2 + nh];
                        MMA16816(cc, aH[mf], bHf[g][nh * 2], bHf[g][nh * 2 + 1]);
                        MMA16816(cc, aH[mf], bLf[g][nh * 2], bLf[g][nh * 2 + 1]);
                        MMA16816(cc, aL[mf], bHf[g][nh * 2], bHf[g][nh * 2 + 1]);
                    }
        }
        __syncthreads();
    }

    #pragma unroll
    for (int mf = 0; mf < 2; mf++) {
        int t = t0 + wm0 + mf * 16 + (lane >> 2);
        #pragma unroll
        for (int nf = 0; nf < 4; nf++) {
            int d = wn0 + nf * 8 + (lane & 3) * 2;
            float* a = acc[mf][nf];
            #pragma unroll
            for (int rr = 0; rr < 2; rr++) {
                int tt = t + rr * 8;
                size_t off = ((size_t)b * TT + tt) * EE + h * DH + d;
                __nv_bfloat16 hi, lo;
                split_bf16(a[rr * 2], hi, lo);
                gA_hi[off] = hi; gA_lo[off] = lo;
                split_bf16(a[rr * 2 + 1], hi, lo);
                gA_hi[off + 1] = hi; gA_lo[off + 1] = lo;
            }
        }
    }
}

// ---------------- K7: logits GEMM (HMMA, 3-stage, 2 CTA/SM, fused expsum) ---
#define GSTAGE 32768
#define GSMEM_BYTES (3 * GSTAGE)
__global__ __launch_bounds__(256, 2) void k_gemm(const float* __restrict__ bias,
                                                 float* __restrict__ C) {
    extern __shared__ __align__(128) char smem[];
    const uint32_t sb = smem_u32(smem);
    const int tid = threadIdx.x;
    const int wid = tid >> 5, lane = tid & 31;
    const int m0 = blockIdx.x * 128;
    const int n0 = blockIdx.y * 128;
    const int wm0 = (wid & 1) * 64;
    const int wn0 = (wid >> 1) * 32;

    float acc[4][4][4];
    #pragma unroll
    for (int i = 0; i < 4; i++)
        #pragma unroll
        for (int j = 0; j < 4; j++)
            #pragma unroll
            for (int q = 0; q < 4; q++) acc[i][j][q] = 0.f;

    auto load_stage = [&](int p, int k0) {
        uint32_t base = sb + p * GSTAGE;
        int kbyte = k0 * 2;
        #pragma unroll
        for (int half = 0; half < 2; half++) {
            int j = tid + half * 256;
            int row = j >> 2, ch = j & 3;
            uint32_t soff = row * 64 + (((ch ^ (row & 3)) & 3) << 4);
            size_t ga = (size_t)(m0 + row) * (EE * 2) + kbyte + ch * 16;
            cpasync16(base + soff,         (const char*)gA_hi + ga);
            cpasync16(base + 8192 + soff,  (const char*)gA_lo + ga);
            int nn = n0 + row; if (nn >= VV) nn = VV - 1;
            size_t gb = (size_t)nn * (EE * 2) + kbyte + ch * 16;
            cpasync16(base + 16384 + soff, (const char*)gW_hi + gb);
            cpasync16(base + 24576 + soff, (const char*)gW_lo + gb);
        }
    };

    load_stage(0, 0);
    CP_COMMIT();
    load_stage(1, 32);
    CP_COMMIT();

    const int NIT = EE / 32;    // 24
    int buf = 0;
    for (int it = 0; it < NIT; it++) {
        if (it + 1 < NIT) { CP_WAIT1(); } else { CP_WAIT0(); }
        __syncthreads();
        if (it + 2 < NIT) {
            int nb = buf + 2; if (nb >= 3) nb -= 3;
            load_stage(nb, (it + 2) * 32);
            CP_COMMIT();
        }
        uint32_t stage = sb + buf * GSTAGE;
        #pragma unroll
        for (int kh = 0; kh < 2; kh++) {
            uint32_t aH[4][4], aL[4][4], bHf[2][4], bLf[2][4];
            #pragma unroll
            for (int mf = 0; mf < 4; mf++) {
                int row = wm0 + mf * 16 + (lane & 7) + ((lane >> 3) & 1) * 8;
                int ch = 2 * kh + (lane >> 4);
                uint32_t ad = stage + row * 64 + (((ch ^ (row & 3)) & 3) << 4);
                LDSM_X4(aH[mf], ad);
                LDSM_X4(aL[mf], ad + 8192);
            }
            #pragma unroll
            for (int g = 0; g < 2; g++) {
                int row = wn0 + g * 16 + (lane & 7) + ((lane >> 4) & 1) * 8;
                int ch = 2 * kh + ((lane >> 3) & 1);
                uint32_t ad = stage + 16384 + row * 64 + (((ch ^ (row & 3)) & 3) << 4);
                LDSM_X4(bHf[g], ad);
                LDSM_X4(bLf[g], ad + 8192);
            }
            #pragma unroll
            for (int mf = 0; mf < 4; mf++)
                #pragma unroll
                for (int g = 0; g < 2; g++)
                    #pragma unroll
                    for (int nh = 0; nh < 2; nh++) {
                        float* c = acc[mf][g * 2 + nh];
                        MMA16816(c, aH[mf], bHf[g][nh * 2], bHf[g][nh * 2 + 1]);
                        MMA16816(c, aH[mf], bLf[g][nh * 2], bLf[g][nh * 2 + 1]);
                        MMA16816(c, aL[mf], bHf[g][nh * 2], bHf[g][nh * 2 + 1]);
                    }
        }
        buf++; if (buf == 3) buf = 0;
    }

    // epilogue: write logits (+bias, scalar stores — VV is odd, rows are only
    // 4B-aligned) and per-row expsum partials (deterministic slots, no atomics)
    const int py = blockIdx.y * 4 + (wid >> 1);
    #pragma unroll
    for (int mf = 0; mf < 4; mf++) {
        int r = m0 + wm0 + mf * 16 + (lane >> 2);
        float* p0 = C + (size_t)r * VV;
        float* p1 = p0 + (size_t)8 * VV;
        float e0 = 0.f, e1 = 0.f;
        #pragma unroll
        for (int nf = 0; nf < 4; nf++) {
            int cc = n0 + wn0 + nf * 8 + (lane & 3) * 2;
            float* a = acc[mf][nf];
            if (cc < VV) {
                float bv = __ldg(&bias[cc]);
                float v0 = a[0] + bv, v2 = a[2] + bv;
                p0[cc] = v0; p1[cc] = v2;
                e0 += __expf(v0);
                e1 += __expf(v2);
            }
            if (cc + 1 < VV) {
                float bv = __ldg(&bias[cc + 1]);
                float v1 = a[1] + bv, v3 = a[3] + bv;
                p0[cc + 1] = v1; p1[cc + 1] = v3;
                e0 += __expf(v1);
                e1 += __expf(v3);
            }
        }
        e0 += __shfl_xor_sync(0xffffffffu, e0, 1);
        e0 += __shfl_xor_sync(0xffffffffu, e0, 2);
        e1 += __shfl_xor_sync(0xffffffffu, e1, 1);
        e1 += __shfl_xor_sync(0xffffffffu, e1, 2);
        if ((lane & 3) == 0) {
            g_part[(size_t)r * NPART + py]       = e0;
            g_part[(size_t)(r + 8) * NPART + py] = e1;
        }
    }
}

// ---------------- K8: per-row lse from partials + target gather -------------
__global__ __launch_bounds__(256) void k_rowloss(const float* __restrict__ logits,
                                                 const int* __restrict__ y) {
    int row = blockIdx.x;
    int tid = threadIdx.x;
    float s = 0.f;
    for (int i = tid; i < NPART; i += 256) s += g_part[(size_t)row * NPART + i];
    __shared__ float ss[256];
    ss[tid] = s;
    __syncthreads();
    for (int off = 128; off > 0; off >>= 1) {
        if (tid < off) ss[tid] += ss[tid + off];
        __syncthreads();
    }
    if (tid == 0) {
        g_rowloss[row] = logf(ss[0]) - logits[(size_t)row * VV + y[row]];
    }
}

// ---------------- K9: mean -> loss scalar -----------------------------------
__global__ void k_loss(float* __restrict__ out) {
    __shared__ float sb[256];
    int tid = threadIdx.x;
    float s = 0.f;
    for (int i = tid; i < NTOK; i += 256) s += g_rowloss[i];
    sb[tid] = s;
    __syncthreads();
    for (int off = 128; off > 0; off >>= 1) {
        if (tid < off) sb[tid] += sb[tid + off];
        __syncthreads();
    }
    if (tid == 0) out[0] = sb[0] / (float)NTOK;
}

// ---------------- launch -----------------------------------------------------
extern "C" void kernel_launch(void* const* d_in, const int* in_sizes, int n_in,
                              void* d_out, int out_size) {
    const int*   x    = (const int*)d_in[0];
    const int*   y    = (const int*)d_in[1];
    const float* tok  = (const float*)d_in[2];
    const float* pos  = (const float*)d_in[3];
    const float* Wq   = (const float*)d_in[4];
    const float* Wk   = (const float*)d_in[5];
    const float* Wv   = (const float*)d_in[6];
    const float* Wout = (const float*)d_in[7];
    const float* bout = (const float*)d_in[8];
    float* out = (float*)d_out;

    cudaFuncSetAttribute(k_projmma, cudaFuncAttributeMaxDynamicSharedMemorySize, PSMEM);
    cudaFuncSetAttribute(k_scores,  cudaFuncAttributeMaxDynamicSharedMemorySize, SSMEM);
    cudaFuncSetAttribute(k_av,      cudaFuncAttributeMaxDynamicSharedMemorySize, ASMEM);
    cudaFuncSetAttribute(k_gemm,    cudaFuncAttributeMaxDynamicSharedMemorySize, GSMEM_BYTES);

    k_embed<<<NTOK * EE / 256, 256>>>(x, tok, pos);
    k_packW<<<NQKV * EE / 256, 256>>>(Wq, Wk, Wv);
    k_cvtW<<<dim3((VV + 31) / 32, EE / 32), dim3(32, 8)>>>(Wout);

    k_projmma<<<dim3(NTOK / 128, NQKV / 128), 256, PSMEM>>>();

    k_scores<<<dim3(16, 16, BH), 256, SSMEM>>>();

    k_colstats<<<dim3(TT / 256, BH), 256>>>();

    k_av<<<dim3(TT / 128, BH), 256, ASMEM>>>();

    k_gemm<<<dim3(NTOK / 128, (VV + 127) / 128), 256, GSMEM_BYTES>>>(bout, out);

    k_rowloss<<<NTOK, 256>>>(out, y);

    long long nlogits = (long long)NTOK * VV;
    if ((long long)out_size > nlogits) {
        k_loss<<<1, 256>>>(out + nlogits);
    }
}

// round 14
// speedup vs baseline: 1.2984x; 1.1617x over previous
#include <cuda_runtime.h>
#include <cuda_bf16.h>
#include <math.h>
#include <stdint.h>

#define BB 2
#define TT 2048
#define EE 768
#define HH 12
#define DH 64
#define VV 50257
#define NTOK (BB*TT)      // 4096
#define BH (BB*HH)        // 24
#define NQKV 2304         // 3*H*Dh
#define NPART 1572        // 393 n-tiles * 4 warp-columns

// ---------------- scratch (device globals; no allocation allowed) ----------
__device__ __nv_bfloat16 g_att[100663296];           // 201 MB scores bf16 [bh][t][s]
__device__ float g_cpart[(size_t)BH*16*2*TT];        // col expsum partials 6.3MB
__device__ float g_cinv[BH*TT];
__device__ float g_rowloss[NTOK];
__device__ float g_part[(size_t)NTOK*NPART];         // per-row expsum partials
__device__ __nv_bfloat16 g_hhi[NTOK*EE];             // embed hi/lo
__device__ __nv_bfloat16 g_hlo[NTOK*EE];
__device__ __nv_bfloat16 gWp_hi[NQKV*EE];            // packed QKV weights [n][e]
__device__ __nv_bfloat16 gWp_lo[NQKV*EE];
__device__ __nv_bfloat16 gq_hi[BH*TT*DH], gq_lo[BH*TT*DH];
__device__ __nv_bfloat16 gk_hi[BH*TT*DH], gk_lo[BH*TT*DH];
__device__ __nv_bfloat16 gvT_hi[BH*DH*TT], gvT_lo[BH*DH*TT];   // v transposed [bh][d][t]
__device__ __nv_bfloat16 gA_hi[NTOK*EE];             // attention out (A of logits GEMM)
__device__ __nv_bfloat16 gA_lo[NTOK*EE];
__device__ __nv_bfloat16 gW_hi[(size_t)VV*EE];       // Wout^T [V][E] K-major
__device__ __nv_bfloat16 gW_lo[(size_t)VV*EE];

// ---------------- PTX helpers ----------------------------------------------
__device__ __forceinline__ uint32_t smem_u32(const void* p) {
    uint32_t a;
    asm("{ .reg .u64 t; cvta.to.shared.u64 t, %1; cvt.u32.u64 %0, t; }" : "=r"(a) : "l"(p));
    return a;
}
__device__ __forceinline__ void cpasync16(uint32_t s, const void* g) {
    asm volatile("cp.async.cg.shared.global [%0], [%1], 16;" :: "r"(s), "l"(g));
}
#define CP_COMMIT() asm volatile("cp.async.commit_group;" ::: "memory")
#define CP_WAIT1()  asm volatile("cp.async.wait_group 1;" ::: "memory")
#define CP_WAIT0()  asm volatile("cp.async.wait_group 0;" ::: "memory")

#define LDSM_X4(r, addr) \
    asm volatile("ldmatrix.sync.aligned.m8n8.x4.shared.b16 {%0,%1,%2,%3}, [%4];" \
        : "=r"((r)[0]), "=r"((r)[1]), "=r"((r)[2]), "=r"((r)[3]) : "r"(addr))

#define MMA16816(c, a, b0, b1) \
    asm volatile("mma.sync.aligned.m16n8k16.row.col.f32.bf16.bf16.f32 " \
        "{%0,%1,%2,%3}, {%4,%5,%6,%7}, {%8,%9}, {%0,%1,%2,%3};" \
        : "+f"((c)[0]), "+f"((c)[1]), "+f"((c)[2]), "+f"((c)[3]) \
        : "r"((a)[0]), "r"((a)[1]), "r"((a)[2]), "r"((a)[3]), "r"(b0), "r"(b1))

__device__ __forceinline__ void split_bf16(float v, __nv_bfloat16& hi, __nv_bfloat16& lo) {
    hi = __float2bfloat16_rn(v);
    lo = __float2bfloat16_rn(v - __bfloat162float(hi));
}

// ---------------- K1: embed -> h hi/lo --------------------------------------
__global__ void k_embed(const int* __restrict__ x, const float* __restrict__ tok,
                        const float* __restrict__ pos) {
    int idx = blockIdx.x * 256 + threadIdx.x;
    int e  = idx % EE;
    int bt = idx / EE;
    int t  = bt % TT;
    float v = tok[(size_t)x[bt] * EE + e] + pos[t * EE + e];
    split_bf16(v, g_hhi[idx], g_hlo[idx]);
}

// ---------------- K2a: pack Wq/Wk/Wv -> [2304][768] bf16 hi/lo --------------
__global__ void k_packW(const float* __restrict__ Wq, const float* __restrict__ Wk,
                        const float* __restrict__ Wv) {
    int idx = blockIdx.x * 256 + threadIdx.x;       // over NQKV*EE
    int n = idx / EE, e = idx % EE;
    int mat = n / (HH * DH);
    int rem = n - mat * (HH * DH);
    int hh = rem >> 6, d = rem & 63;
    const float* W = (mat == 0 ? Wq : (mat == 1 ? Wk : Wv));
    float v = W[((size_t)hh * EE + e) * DH + d];
    split_bf16(v, gWp_hi[idx], gWp_lo[idx]);
}

// ---------------- K2b: transpose Wout [E][V] -> [V][E] bf16 hi/lo -----------
__global__ __launch_bounds__(256) void k_cvtW(const float* __restrict__ W) {
    __shared__ float tile[32][33];
    int n0 = blockIdx.x * 32;
    int k0 = blockIdx.y * 32;
    int tx = threadIdx.x, ty = threadIdx.y;   // 32 x 8
    #pragma unroll
    for (int j = 0; j < 4; j++) {
        int k = k0 + ty + j * 8;
        int n = n0 + tx;
        tile[ty + j * 8][tx] = (n < VV) ? W[(size_t)k * VV + n] : 0.f;
    }
    __syncthreads();
    #pragma unroll
    for (int j = 0; j < 4; j++) {
        int n = n0 + ty + j * 8;
        if (n < VV) {
            float v = tile[tx][ty + j * 8];
            size_t off = (size_t)n * EE + k0 + tx;
            split_bf16(v, gW_hi[off], gW_lo[off]);
        }
    }
}

// ---------------- K3: fused QKV projection (HMMA, hi/lo 3-pass) --------------
#define PSTAGE 32768
#define PSMEM  (2 * PSTAGE)
__global__ __launch_bounds__(256) void k_projmma() {
    extern __shared__ __align__(128) char smem[];
    const uint32_t sb = smem_u32(smem);
    const int tid = threadIdx.x;
    const int wid = tid >> 5, lane = tid & 31;
    const int m0 = blockIdx.x * 128;
    const int n0 = blockIdx.y * 128;
    const int wm0 = (wid & 1) * 64;
    const int wn0 = (wid >> 1) * 32;

    float acc[4][4][4];
    #pragma unroll
    for (int i = 0; i < 4; i++)
        #pragma unroll
        for (int j = 0; j < 4; j++)
            #pragma unroll
            for (int q = 0; q < 4; q++) acc[i][j][q] = 0.f;

    auto load_stage = [&](int p, int k0) {
        uint32_t base = sb + p * PSTAGE;
        int kbyte = k0 * 2;
        #pragma unroll
        for (int half = 0; half < 2; half++) {
            int j = tid + half * 256;
            int row = j >> 2, ch = j & 3;
            uint32_t soff = row * 64 + (((ch ^ (row & 3)) & 3) << 4);
            size_t ga = (size_t)(m0 + row) * (EE * 2) + kbyte + ch * 16;
            cpasync16(base + soff,         (const char*)g_hhi + ga);
            cpasync16(base + 8192 + soff,  (const char*)g_hlo + ga);
            size_t gb = (size_t)(n0 + row) * (EE * 2) + kbyte + ch * 16;
            cpasync16(base + 16384 + soff, (const char*)gWp_hi + gb);
            cpasync16(base + 24576 + soff, (const char*)gWp_lo + gb);
        }
    };

    load_stage(0, 0);
    CP_COMMIT();
    const int NIT = EE / 32;
    for (int it = 0; it < NIT; it++) {
        int p = it & 1;
        if (it + 1 < NIT) {
            load_stage(p ^ 1, (it + 1) * 32);
            CP_COMMIT();
            CP_WAIT1();
        } else {
            CP_WAIT0();
        }
        __syncthreads();
        uint32_t stage = sb + p * PSTAGE;
        #pragma unroll
        for (int kh = 0; kh < 2; kh++) {
            uint32_t aH[4][4], aL[4][4], bHf[2][4], bLf[2][4];
            #pragma unroll
            for (int mf = 0; mf < 4; mf++) {
                int row = wm0 + mf * 16 + (lane & 7) + ((lane >> 3) & 1) * 8;
                int ch = 2 * kh + (lane >> 4);
                uint32_t ad = stage + row * 64 + (((ch ^ (row & 3)) & 3) << 4);
                LDSM_X4(aH[mf], ad);
                LDSM_X4(aL[mf], ad + 8192);
            }
            #pragma unroll
            for (int g = 0; g < 2; g++) {
                int row = wn0 + g * 16 + (lane & 7) + ((lane >> 4) & 1) * 8;
                int ch = 2 * kh + ((lane >> 3) & 1);
                uint32_t ad = stage + 16384 + row * 64 + (((ch ^ (row & 3)) & 3) << 4);
                LDSM_X4(bHf[g], ad);
                LDSM_X4(bLf[g], ad + 8192);
            }
            #pragma unroll
            for (int mf = 0; mf < 4; mf++)
                #pragma unroll
                for (int g = 0; g < 2; g++)
                    #pragma unroll
                    for (int nh = 0; nh < 2; nh++) {
                        float* c = acc[mf][g * 2 + nh];
                        MMA16816(c, aH[mf], bHf[g][nh * 2], bHf[g][nh * 2 + 1]);
                        MMA16816(c, aH[mf], bLf[g][nh * 2], bLf[g][nh * 2 + 1]);
                        MMA16816(c, aL[mf], bHf[g][nh * 2], bHf[g][nh * 2 + 1]);
                    }
        }
        __syncthreads();
    }

    // epilogue: scatter to q/k hi/lo [bh][t][d] and v^T hi/lo [bh][d][t]
    const int mat = n0 / (HH * DH);     // tile never crosses a matrix boundary
    #pragma unroll
    for (int mf = 0; mf < 4; mf++) {
        int r0 = m0 + wm0 + mf * 16 + (lane >> 2);
        #pragma unroll
        for (int nf = 0; nf < 4; nf++) {
            float* a = acc[mf][nf];
            #pragma unroll
            for (int c2 = 0; c2 < 2; c2++) {
                int n = n0 + wn0 + nf * 8 + (lane & 3) * 2 + c2;
                int rem = n - mat * (HH * DH);
                int hh = rem >> 6, d = rem & 63;
                #pragma unroll
                for (int rr = 0; rr < 2; rr++) {
                    int r = r0 + rr * 8;
                    int b = r >> 11, t = r & 2047;
                    int bh = b * HH + hh;
                    float v = a[c2 + rr * 2];
                    __nv_bfloat16 hi, lo;
                    split_bf16(v, hi, lo);
                    if (mat == 0) {
                        size_t off = ((size_t)bh * TT + t) * DH + d;
                        gq_hi[off] = hi; gq_lo[off] = lo;
                    } else if (mat == 1) {
                        size_t off = ((size_t)bh * TT + t) * DH + d;
                        gk_hi[off] = hi; gk_lo[off] = lo;
                    } else {
                        size_t off = ((size_t)bh * DH + d) * TT + t;
                        gvT_hi[off] = hi; gvT_lo[off] = lo;
                    }
                }
            }
        }
    }
}

// ---------------- K4: scores via HMMA; bf16 att out + fused col expsums -----
#define SSMEM 65536
__global__ __launch_bounds__(256) void k_scores() {
    int zs = blockIdx.x, zt = blockIdx.y, bh = blockIdx.z;
    if (zs > zt) return;
    int s0 = zs * 128, t0 = zt * 128;
    extern __shared__ __align__(128) char smem[];
    const uint32_t sb = smem_u32(smem);
    const int tid = threadIdx.x;
    const int wid = tid >> 5, lane = tid & 31;
    const int wm0 = (wid & 1) * 64;
    const int wn0 = (wid >> 1) * 32;

    #pragma unroll
    for (int i = 0; i < 4; i++) {
        int j = tid + i * 256;                 // 0..1023
        int row = j >> 3, ch = j & 7;
        uint32_t soff = row * 128 + (((ch ^ (row & 7)) & 7) << 4);
        size_t gq = ((size_t)bh * TT + t0 + row) * 128 + ch * 16;
        size_t gk = ((size_t)bh * TT + s0 + row) * 128 + ch * 16;
        cpasync16(sb + soff,         (const char*)gq_hi + gq);
        cpasync16(sb + 16384 + soff, (const char*)gq_lo + gq);
        cpasync16(sb + 32768 + soff, (const char*)gk_hi + gk);
        cpasync16(sb + 49152 + soff, (const char*)gk_lo + gk);
    }
    CP_COMMIT();
    CP_WAIT0();
    __syncthreads();

    float acc[4][4][4];
    #pragma unroll
    for (int i = 0; i < 4; i++)
        #pragma unroll
        for (int j = 0; j < 4; j++)
            #pragma unroll
            for (int q = 0; q < 4; q++) acc[i][j][q] = 0.f;

    #pragma unroll
    for (int kh = 0; kh < 4; kh++) {
        uint32_t aH[4][4], aL[4][4], bHf[2][4], bLf[2][4];
        #pragma unroll
        for (int mf = 0; mf < 4; mf++) {
            int row = wm0 + mf * 16 + (lane & 7) + ((lane >> 3) & 1) * 8;
            int ch = 2 * kh + (lane >> 4);
            uint32_t ad = sb + row * 128 + (((ch ^ (row & 7)) & 7) << 4);
            LDSM_X4(aH[mf], ad);
            LDSM_X4(aL[mf], ad + 16384);
        }
        #pragma unroll
        for (int g = 0; g < 2; g++) {
            int row = wn0 + g * 16 + (lane & 7) + ((lane >> 4) & 1) * 8;
            int ch = 2 * kh + ((lane >> 3) & 1);
            uint32_t ad = sb + 32768 + row * 128 + (((ch ^ (row & 7)) & 7) << 4);
            LDSM_X4(bHf[g], ad);
            LDSM_X4(bLf[g], ad + 16384);
        }
        #pragma unroll
        for (int mf = 0; mf < 4; mf++)
            #pragma unroll
            for (int g = 0; g < 2; g++)
                #pragma unroll
                for (int nh = 0; nh < 2; nh++) {
                    float* c = acc[mf][g * 2 + nh];
                    MMA16816(c, aH[mf], bHf[g][nh * 2], bHf[g][nh * 2 + 1]);
                    MMA16816(c, aH[mf], bLf[g][nh * 2], bLf[g][nh * 2 + 1]);
                    MMA16816(c, aL[mf], bHf[g][nh * 2], bHf[g][nh * 2 + 1]);
                }
    }

    // epilogue: bf16 score store + masked per-column exp partial sums
    __nv_bfloat16* out = g_att + (size_t)bh * TT * TT;
    float csum[4][2];
    #pragma unroll
    for (int nf = 0; nf < 4; nf++) { csum[nf][0] = 0.f; csum[nf][1] = 0.f; }
    #pragma unroll
    for (int mf = 0; mf < 4; mf++) {
        int t = t0 + wm0 + mf * 16 + (lane >> 2);
        __nv_bfloat16* p0 = out + (size_t)t * TT;
        __nv_bfloat16* p1 = p0 + (size_t)8 * TT;
        #pragma unroll
        for (int nf = 0; nf < 4; nf++) {
            int s = s0 + wn0 + nf * 8 + (lane & 3) * 2;
            float* a = acc[mf][nf];
            float v0 = a[0] * 8.0f, v1 = a[1] * 8.0f;
            float v2 = a[2] * 8.0f, v3 = a[3] * 8.0f;
            *(__nv_bfloat162*)(p0 + s) = __floats2bfloat162_rn(v0, v1);
            *(__nv_bfloat162*)(p1 + s) = __floats2bfloat162_rn(v2, v3);
            csum[nf][0] += (s     <= t     ? __expf(v0) : 0.f)
                         + (s     <= t + 8 ? __expf(v2) : 0.f);
            csum[nf][1] += (s + 1 <= t     ? __expf(v1) : 0.f)
                         + (s + 1 <= t + 8 ? __expf(v3) : 0.f);
        }
    }
    // reduce over the 8 lanes sharing each column (lane>>2 varies)
    #pragma unroll
    for (int nf = 0; nf < 4; nf++) {
        #pragma unroll
        for (int k = 0; k < 2; k++) {
            csum[nf][k] += __shfl_xor_sync(0xffffffffu, csum[nf][k], 4);
            csum[nf][k] += __shfl_xor_sync(0xffffffffu, csum[nf][k], 8);
            csum[nf][k] += __shfl_xor_sync(0xffffffffu, csum[nf][k], 16);
        }
    }
    if (lane < 4) {
        size_t base = (((size_t)bh * 16 + zt) * 2 + (wid & 1)) * TT;
        #pragma unroll
        for (int nf = 0; nf < 4; nf++) {
            int s = s0 + wn0 + nf * 8 + lane * 2;
            *(float2*)&g_cpart[base + s] = make_float2(csum[nf][0], csum[nf][1]);
        }
    }
}

// ---------------- K5: per-column softmax sums from partials ------------------
__global__ void k_colstats() {
    int bh = blockIdx.y;
    int s = blockIdx.x * 256 + threadIdx.x;
    int zs = s >> 7;
    float sum = 0.f;
    for (int zt = zs; zt < 16; zt++) {
        size_t base = (((size_t)bh * 16 + zt) * 2) * TT;
        sum += g_cpart[base + s] + g_cpart[base + TT + s];
    }
    g_cinv[bh * TT + s] = 1.0f / sum;
}

// ---------------- K6: o = softmax(att) @ v via HMMA -------------------------
#define ASMEM 49152
__global__ __launch_bounds__(256) void k_av() {
    int zt = blockIdx.x, bh = blockIdx.y;
    int t0 = zt * 128;
    int b = bh / HH, h = bh % HH;
    extern __shared__ __align__(128) char smem[];
    const uint32_t sb = smem_u32(smem);
    char* whi = smem;
    char* wlo = smem + 16384;
    const int tid = threadIdx.x;
    const int wid = tid >> 5, lane = tid & 31;
    const int wm0 = (wid & 3) * 32;
    const int wn0 = (wid >> 2) * 32;

    const __nv_bfloat16* att = g_att + (size_t)bh * TT * TT;
    const float* ci  = g_cinv + bh * TT;

    float acc[2][4][4];
    #pragma unroll
    for (int i = 0; i < 2; i++)
        #pragma unroll
        for (int j = 0; j < 4; j++)
            #pragma unroll
            for (int q = 0; q < 4; q++) acc[i][j][q] = 0.f;

    int nchunks = 2 * zt + 2;
    for (int c = 0; c < nchunks; c++) {
        int s0 = c * 64;
        #pragma unroll
        for (int i = 0; i < 2; i++) {
            int j = tid + i * 256;             // 0..511
            int row = j >> 3, ch = j & 7;
            uint32_t soff = row * 128 + (((ch ^ (row & 7)) & 7) << 4);
            size_t gv = ((size_t)bh * DH + row) * (TT * 2) + s0 * 2 + ch * 16;
            cpasync16(sb + 32768 + soff, (const char*)gvT_hi + gv);
            cpasync16(sb + 40960 + soff, (const char*)gvT_lo + gv);
        }
        CP_COMMIT();
        // w tile: 128 t-rows x 64 s processed as bf162 pairs
        #pragma unroll
        for (int i = 0; i < 16; i++) {
            int j = tid + i * 256;             // 0..4095 pairs
            int row = j >> 5, p = j & 31;
            int sc = p * 2;
            int t = t0 + row, s = s0 + sc;
            __nv_bfloat162 av = *(const __nv_bfloat162*)(att + (size_t)t * TT + s);
            float w0 = (s     <= t) ? __expf(__bfloat162float(av.x)) * ci[s]     : 0.f;
            float w1 = (s + 1 <= t) ? __expf(__bfloat162float(av.y)) * ci[s + 1] : 0.f;
            __nv_bfloat16 h0, l0, h1, l1;
            split_bf16(w0, h0, l0);
            split_bf16(w1, h1, l1);
            int ch = sc >> 3;
            uint32_t soff = row * 128 + (((ch ^ (row & 7)) & 7) << 4) + (sc & 7) * 2;
            *(__nv_bfloat162*)(whi + soff) = __halves2bfloat162(h0, h1);
            *(__nv_bfloat162*)(wlo + soff) = __halves2bfloat162(l0, l1);
        }
        CP_WAIT0();
        __syncthreads();

        #pragma unroll
        for (int kh = 0; kh < 4; kh++) {
            uint32_t aH[2][4], aL[2][4], bHf[2][4], bLf[2][4];
            #pragma unroll
            for (int mf = 0; mf < 2; mf++) {
                int row = wm0 + mf * 16 + (lane & 7) + ((lane >> 3) & 1) * 8;
                int ch = 2 * kh + (lane >> 4);
                uint32_t ad = sb + row * 128 + (((ch ^ (row & 7)) & 7) << 4);
                LDSM_X4(aH[mf], ad);
                LDSM_X4(aL[mf], ad + 16384);
            }
            #pragma unroll
            for (int g = 0; g < 2; g++) {
                int row = wn0 + g * 16 + (lane & 7) + ((lane >> 4) & 1) * 8;
                int ch = 2 * kh + ((lane >> 3) & 1);
                uint32_t ad = sb + 32768 + row * 128 + (((ch ^ (row & 7)) & 7) << 4);
                LDSM_X4(bHf[g], ad);
                LDSM_X4(bLf[g], ad + 8192);
            }
            #pragma unroll
            for (int mf = 0; mf < 2; mf++)
                #pragma unroll
                for (int g = 0; g < 2; g++)
                    #pragma unroll
                    for (int nh = 0; nh < 2; nh++) {
                        float* cc = acc[mf][g * 2 + nh];
                        MMA16816(cc, aH[mf], bHf[g][nh * 2], bHf[g][nh * 2 + 1]);
                        MMA16816(cc, aH[mf], bLf[g][nh * 2], bLf[g][nh * 2 + 1]);
                        MMA16816(cc, aL[mf], bHf[g][nh * 2], bHf[g][nh * 2 + 1]);
                    }
        }
        __syncthreads();
    }

    #pragma unroll
    for (int mf = 0; mf < 2; mf++) {
        int t = t0 + wm0 + mf * 16 + (lane >> 2);
        #pragma unroll
        for (int nf = 0; nf < 4; nf++) {
            int d = wn0 + nf * 8 + (lane & 3) * 2;
            float* a = acc[mf][nf];
            #pragma unroll
            for (int rr = 0; rr < 2; rr++) {
                int tt = t + rr * 8;
                size_t off = ((size_t)b * TT + tt) * EE + h * DH + d;
                __nv_bfloat16 hi, lo;
                split_bf16(a[rr * 2], hi, lo);
                gA_hi[off] = hi; gA_lo[off] = lo;
                split_bf16(a[rr * 2 + 1], hi, lo);
                gA_hi[off + 1] = hi; gA_lo[off + 1] = lo;
            }
        }
    }
}

// ---------------- K7: logits GEMM (HMMA, 3-stage, 2 CTA/SM, fused expsum) ---
#define GSTAGE 32768
#define GSMEM_BYTES (3 * GSTAGE)
__global__ __launch_bounds__(256, 2) void k_gemm(const float* __restrict__ bias,
                                                 float* __restrict__ C) {
    extern __shared__ __align__(128) char smem[];
    const uint32_t sb = smem_u32(smem);
    const int tid = threadIdx.x;
    const int wid = tid >> 5, lane = tid & 31;
    const int m0 = blockIdx.x * 128;
    const int n0 = blockIdx.y * 128;
    const int wm0 = (wid & 1) * 64;
    const int wn0 = (wid >> 1) * 32;

    float acc[4][4][4];
    #pragma unroll
    for (int i = 0; i < 4; i++)
        #pragma unroll
        for (int j = 0; j < 4; j++)
            #pragma unroll
            for (int q = 0; q < 4; q++) acc[i][j][q] = 0.f;

    auto load_stage = [&](int p, int k0) {
        uint32_t base = sb + p * GSTAGE;
        int kbyte = k0 * 2;
        #pragma unroll
        for (int half = 0; half < 2; half++) {
            int j = tid + half * 256;
            int row = j >> 2, ch = j & 3;
            uint32_t soff = row * 64 + (((ch ^ (row & 3)) & 3) << 4);
            size_t ga = (size_t)(m0 + row) * (EE * 2) + kbyte + ch * 16;
            cpasync16(base + soff,         (const char*)gA_hi + ga);
            cpasync16(base + 8192 + soff,  (const char*)gA_lo + ga);
            int nn = n0 + row; if (nn >= VV) nn = VV - 1;
            size_t gb = (size_t)nn * (EE * 2) + kbyte + ch * 16;
            cpasync16(base + 16384 + soff, (const char*)gW_hi + gb);
            cpasync16(base + 24576 + soff, (const char*)gW_lo + gb);
        }
    };

    load_stage(0, 0);
    CP_COMMIT();
    load_stage(1, 32);
    CP_COMMIT();

    const int NIT = EE / 32;    // 24
    int buf = 0;
    for (int it = 0; it < NIT; it++) {
        if (it + 1 < NIT) { CP_WAIT1(); } else { CP_WAIT0(); }
        __syncthreads();
        if (it + 2 < NIT) {
            int nb = buf + 2; if (nb >= 3) nb -= 3;
            load_stage(nb, (it + 2) * 32);
            CP_COMMIT();
        }
        uint32_t stage = sb + buf * GSTAGE;
        #pragma unroll
        for (int kh = 0; kh < 2; kh++) {
            uint32_t aH[4][4], aL[4][4], bHf[2][4], bLf[2][4];
            #pragma unroll
            for (int mf = 0; mf < 4; mf++) {
                int row = wm0 + mf * 16 + (lane & 7) + ((lane >> 3) & 1) * 8;
                int ch = 2 * kh + (lane >> 4);
                uint32_t ad = stage + row * 64 + (((ch ^ (row & 3)) & 3) << 4);
                LDSM_X4(aH[mf], ad);
                LDSM_X4(aL[mf], ad + 8192);
            }
            #pragma unroll
            for (int g = 0; g < 2; g++) {
                int row = wn0 + g * 16 + (lane & 7) + ((lane >> 4) & 1) * 8;
                int ch = 2 * kh + ((lane >> 3) & 1);
                uint32_t ad = stage + 16384 + row * 64 + (((ch ^ (row & 3)) & 3) << 4);
                LDSM_X4(bHf[g], ad);
                LDSM_X4(bLf[g], ad + 8192);
            }
            #pragma unroll
            for (int mf = 0; mf < 4; mf++)
                #pragma unroll
                for (int g = 0; g < 2; g++)
                    #pragma unroll
                    for (int nh = 0; nh < 2; nh++) {
                        float* c = acc[mf][g * 2 + nh];
                        MMA16816(c, aH[mf], bHf[g][nh * 2], bHf[g][nh * 2 + 1]);
                        MMA16816(c, aH[mf], bLf[g][nh * 2], bLf[g][nh * 2 + 1]);
                        MMA16816(c, aL[mf], bHf[g][nh * 2], bHf[g][nh * 2 + 1]);
                    }
        }
        buf++; if (buf == 3) buf = 0;
    }

    // epilogue: scalar logit stores (VV odd -> 4B-aligned rows) + expsum partials
    const int py = blockIdx.y * 4 + (wid >> 1);
    #pragma unroll
    for (int mf = 0; mf < 4; mf++) {
        int r = m0 + wm0 + mf * 16 + (lane >> 2);
        float* p0 = C + (size_t)r * VV;
        float* p1 = p0 + (size_t)8 * VV;
        float e0 = 0.f, e1 = 0.f;
        #pragma unroll
        for (int nf = 0; nf < 4; nf++) {
            int cc = n0 + wn0 + nf * 8 + (lane & 3) * 2;
            float* a = acc[mf][nf];
            if (cc < VV) {
                float bv = __ldg(&bias[cc]);
                float v0 = a[0] + bv, v2 = a[2] + bv;
                p0[cc] = v0; p1[cc] = v2;
                e0 += __expf(v0);
                e1 += __expf(v2);
            }
            if (cc + 1 < VV) {
                float bv = __ldg(&bias[cc + 1]);
                float v1 = a[1] + bv, v3 = a[3] + bv;
                p0[cc + 1] = v1; p1[cc + 1] = v3;
                e0 += __expf(v1);
                e1 += __expf(v3);
            }
        }
        e0 += __shfl_xor_sync(0xffffffffu, e0, 1);
        e0 += __shfl_xor_sync(0xffffffffu, e0, 2);
        e1 += __shfl_xor_sync(0xffffffffu, e1, 1);
        e1 += __shfl_xor_sync(0xffffffffu, e1, 2);
        if ((lane & 3) == 0) {
            g_part[(size_t)r * NPART + py]       = e0;
            g_part[(size_t)(r + 8) * NPART + py] = e1;
        }
    }
}

// ---------------- K8: per-row lse from partials + target gather -------------
__global__ __launch_bounds__(256) void k_rowloss(const float* __restrict__ logits,
                                                 const int* __restrict__ y) {
    int row = blockIdx.x;
    int tid = threadIdx.x;
    float s = 0.f;
    for (int i = tid; i < NPART; i += 256) s += g_part[(size_t)row * NPART + i];
    __shared__ float ss[256];
    ss[tid] = s;
    __syncthreads();
    for (int off = 128; off > 0; off >>= 1) {
        if (tid < off) ss[tid] += ss[tid + off];
        __syncthreads();
    }
    if (tid == 0) {
        g_rowloss[row] = logf(ss[0]) - logits[(size_t)row * VV + y[row]];
    }
}

// ---------------- K9: mean -> loss scalar -----------------------------------
__global__ void k_loss(float* __restrict__ out) {
    __shared__ float sb[256];
    int tid = threadIdx.x;
    float s = 0.f;
    for (int i = tid; i < NTOK; i += 256) s += g_rowloss[i];
    sb[tid] = s;
    __syncthreads();
    for (int off = 128; off > 0; off >>= 1) {
        if (tid < off) sb[tid] += sb[tid + off];
        __syncthreads();
    }
    if (tid == 0) out[0] = sb[0] / (float)NTOK;
}

// ---------------- launch -----------------------------------------------------
extern "C" void kernel_launch(void* const* d_in, const int* in_sizes, int n_in,
                              void* d_out, int out_size) {
    const int*   x    = (const int*)d_in[0];
    const int*   y    = (const int*)d_in[1];
    const float* tok  = (const float*)d_in[2];
    const float* pos  = (const float*)d_in[3];
    const float* Wq   = (const float*)d_in[4];
    const float* Wk   = (const float*)d_in[5];
    const float* Wv   = (const float*)d_in[6];
    const float* Wout = (const float*)d_in[7];
    const float* bout = (const float*)d_in[8];
    float* out = (float*)d_out;

    cudaFuncSetAttribute(k_projmma, cudaFuncAttributeMaxDynamicSharedMemorySize, PSMEM);
    cudaFuncSetAttribute(k_scores,  cudaFuncAttributeMaxDynamicSharedMemorySize, SSMEM);
    cudaFuncSetAttribute(k_av,      cudaFuncAttributeMaxDynamicSharedMemorySize, ASMEM);
    cudaFuncSetAttribute(k_gemm,    cudaFuncAttributeMaxDynamicSharedMemorySize, GSMEM_BYTES);

    k_embed<<<NTOK * EE / 256, 256>>>(x, tok, pos);
    k_packW<<<NQKV * EE / 256, 256>>>(Wq, Wk, Wv);
    k_cvtW<<<dim3((VV + 31) / 32, EE / 32), dim3(32, 8)>>>(Wout);

    k_projmma<<<dim3(NTOK / 128, NQKV / 128), 256, PSMEM>>>();

    k_scores<<<dim3(16, 16, BH), 256, SSMEM>>>();

    k_colstats<<<dim3(TT / 256, BH), 256>>>();

    k_av<<<dim3(TT / 128, BH), 256, ASMEM>>>();

    k_gemm<<<dim3(NTOK / 128, (VV + 127) / 128), 256, GSMEM_BYTES>>>(bout, out);

    k_rowloss<<<NTOK, 256>>>(out, y);

    long long nlogits = (long long)NTOK * VV;
    if ((long long)out_size > nlogits) {
        k_loss<<<1, 256>>>(out + nlogits);
    }
}

// round 15
// speedup vs baseline: 1.6999x; 1.3092x over previous
#include <cuda_runtime.h>
#include <cuda_bf16.h>
#include <cuda_fp16.h>
#include <math.h>
#include <stdint.h>

#define BB 2
#define TT 2048
#define EE 768
#define HH 12
#define DH 64
#define VV 50257
#define NTOK (BB*TT)      // 4096
#define BH (BB*HH)        // 24
#define NQKV 2304         // 3*H*Dh
#define NPART 1572        // 393 n-tiles * 4 warp-columns

// ---------------- scratch (device globals; no allocation allowed) ----------
__device__ __nv_bfloat16 g_att[100663296];           // 201 MB scores bf16 [bh][t][s]
__device__ float g_cpart[(size_t)BH*16*2*TT];        // col expsum partials 6.3MB
__device__ float g_cinv[BH*TT];
__device__ float g_rowloss[NTOK];
__device__ float g_part[(size_t)NTOK*NPART];         // per-row expsum partials
__device__ __nv_bfloat16 g_hhi[NTOK*EE];             // embed hi/lo
__device__ __nv_bfloat16 g_hlo[NTOK*EE];
__device__ __nv_bfloat16 gWp_hi[NQKV*EE];            // packed QKV weights [n][e]
__device__ __nv_bfloat16 gWp_lo[NQKV*EE];
__device__ __nv_bfloat16 gq_hi[BH*TT*DH], gq_lo[BH*TT*DH];
__device__ __nv_bfloat16 gk_hi[BH*TT*DH], gk_lo[BH*TT*DH];
__device__ __nv_bfloat16 gvT_hi[BH*DH*TT], gvT_lo[BH*DH*TT];   // v transposed [bh][d][t]
__device__ __half gA_h[NTOK*EE];                     // attention out, fp16 (A of logits)
__device__ __half gWh_hi[(size_t)VV*EE];             // Wout^T [V][E] fp16 hi/lo
__device__ __half gWh_lo[(size_t)VV*EE];

// ---------------- PTX helpers ----------------------------------------------
__device__ __forceinline__ uint32_t smem_u32(const void* p) {
    uint32_t a;
    asm("{ .reg .u64 t; cvta.to.shared.u64 t, %1; cvt.u32.u64 %0, t; }" : "=r"(a) : "l"(p));
    return a;
}
__device__ __forceinline__ void cpasync16(uint32_t s, const void* g) {
    asm volatile("cp.async.cg.shared.global [%0], [%1], 16;" :: "r"(s), "l"(g));
}
#define CP_COMMIT() asm volatile("cp.async.commit_group;" ::: "memory")
#define CP_WAIT1()  asm volatile("cp.async.wait_group 1;" ::: "memory")
#define CP_WAIT0()  asm volatile("cp.async.wait_group 0;" ::: "memory")

#define LDSM_X4(r, addr) \
    asm volatile("ldmatrix.sync.aligned.m8n8.x4.shared.b16 {%0,%1,%2,%3}, [%4];" \
        : "=r"((r)[0]), "=r"((r)[1]), "=r"((r)[2]), "=r"((r)[3]) : "r"(addr))

#define MMA16816(c, a, b0, b1) \
    asm volatile("mma.sync.aligned.m16n8k16.row.col.f32.bf16.bf16.f32 " \
        "{%0,%1,%2,%3}, {%4,%5,%6,%7}, {%8,%9}, {%0,%1,%2,%3};" \
        : "+f"((c)[0]), "+f"((c)[1]), "+f"((c)[2]), "+f"((c)[3]) \
        : "r"((a)[0]), "r"((a)[1]), "r"((a)[2]), "r"((a)[3]), "r"(b0), "r"(b1))

#define MMAF16(c, a, b0, b1) \
    asm volatile("mma.sync.aligned.m16n8k16.row.col.f32.f16.f16.f32 " \
        "{%0,%1,%2,%3}, {%4,%5,%6,%7}, {%8,%9}, {%0,%1,%2,%3};" \
        : "+f"((c)[0]), "+f"((c)[1]), "+f"((c)[2]), "+f"((c)[3]) \
        : "r"((a)[0]), "r"((a)[1]), "r"((a)[2]), "r"((a)[3]), "r"(b0), "r"(b1))

__device__ __forceinline__ void split_bf16(float v, __nv_bfloat16& hi, __nv_bfloat16& lo) {
    hi = __float2bfloat16_rn(v);
    lo = __float2bfloat16_rn(v - __bfloat162float(hi));
}

// ---------------- K1: embed -> h hi/lo --------------------------------------
__global__ void k_embed(const int* __restrict__ x, const float* __restrict__ tok,
                        const float* __restrict__ pos) {
    int idx = blockIdx.x * 256 + threadIdx.x;
    int e  = idx % EE;
    int bt = idx / EE;
    int t  = bt % TT;
    float v = tok[(size_t)x[bt] * EE + e] + pos[t * EE + e];
    split_bf16(v, g_hhi[idx], g_hlo[idx]);
}

// ---------------- K2a: pack Wq/Wk/Wv -> [2304][768] bf16 hi/lo --------------
__global__ void k_packW(const float* __restrict__ Wq, const float* __restrict__ Wk,
                        const float* __restrict__ Wv) {
    int idx = blockIdx.x * 256 + threadIdx.x;       // over NQKV*EE
    int n = idx / EE, e = idx % EE;
    int mat = n / (HH * DH);
    int rem = n - mat * (HH * DH);
    int hh = rem >> 6, d = rem & 63;
    const float* W = (mat == 0 ? Wq : (mat == 1 ? Wk : Wv));
    float v = W[((size_t)hh * EE + e) * DH + d];
    split_bf16(v, gWp_hi[idx], gWp_lo[idx]);
}

// ---------------- K2b: transpose Wout [E][V] -> [V][E] fp16 hi/lo -----------
__global__ __launch_bounds__(256) void k_cvtW(const float* __restrict__ W) {
    __shared__ float tile[32][33];
    int n0 = blockIdx.x * 32;
    int k0 = blockIdx.y * 32;
    int tx = threadIdx.x, ty = threadIdx.y;   // 32 x 8
    #pragma unroll
    for (int j = 0; j < 4; j++) {
        int k = k0 + ty + j * 8;
        int n = n0 + tx;
        tile[ty + j * 8][tx] = (n < VV) ? W[(size_t)k * VV + n] : 0.f;
    }
    __syncthreads();
    #pragma unroll
    for (int j = 0; j < 4; j++) {
        int n = n0 + ty + j * 8;
        if (n < VV) {
            float v = tile[tx][ty + j * 8];
            size_t off = (size_t)n * EE + k0 + tx;
            __half hv = __float2half_rn(v);
            gWh_hi[off] = hv;
            gWh_lo[off] = __float2half_rn(v - __half2float(hv));
        }
    }
}

// ---------------- K3: fused QKV projection (HMMA, hi/lo 3-pass) --------------
#define PSTAGE 32768
#define PSMEM  (2 * PSTAGE)
__global__ __launch_bounds__(256) void k_projmma() {
    extern __shared__ __align__(128) char smem[];
    const uint32_t sb = smem_u32(smem);
    const int tid = threadIdx.x;
    const int wid = tid >> 5, lane = tid & 31;
    const int m0 = blockIdx.x * 128;
    const int n0 = blockIdx.y * 128;
    const int wm0 = (wid & 1) * 64;
    const int wn0 = (wid >> 1) * 32;

    float acc[4][4][4];
    #pragma unroll
    for (int i = 0; i < 4; i++)
        #pragma unroll
        for (int j = 0; j < 4; j++)
            #pragma unroll
            for (int q = 0; q < 4; q++) acc[i][j][q] = 0.f;

    auto load_stage = [&](int p, int k0) {
        uint32_t base = sb + p * PSTAGE;
        int kbyte = k0 * 2;
        #pragma unroll
        for (int half = 0; half < 2; half++) {
            int j = tid + half * 256;
            int row = j >> 2, ch = j & 3;
            uint32_t soff = row * 64 + (((ch ^ (row & 3)) & 3) << 4);
            size_t ga = (size_t)(m0 + row) * (EE * 2) + kbyte + ch * 16;
            cpasync16(base + soff,         (const char*)g_hhi + ga);
            cpasync16(base + 8192 + soff,  (const char*)g_hlo + ga);
            size_t gb = (size_t)(n0 + row) * (EE * 2) + kbyte + ch * 16;
            cpasync16(base + 16384 + soff, (const char*)gWp_hi + gb);
            cpasync16(base + 24576 + soff, (const char*)gWp_lo + gb);
        }
    };

    load_stage(0, 0);
    CP_COMMIT();
    const int NIT = EE / 32;
    for (int it = 0; it < NIT; it++) {
        int p = it & 1;
        if (it + 1 < NIT) {
            load_stage(p ^ 1, (it + 1) * 32);
            CP_COMMIT();
            CP_WAIT1();
        } else {
            CP_WAIT0();
        }
        __syncthreads();
        uint32_t stage = sb + p * PSTAGE;
        #pragma unroll
        for (int kh = 0; kh < 2; kh++) {
            uint32_t aH[4][4], aL[4][4], bHf[2][4], bLf[2][4];
            #pragma unroll
            for (int mf = 0; mf < 4; mf++) {
                int row = wm0 + mf * 16 + (lane & 7) + ((lane >> 3) & 1) * 8;
                int ch = 2 * kh + (lane >> 4);
                uint32_t ad = stage + row * 64 + (((ch ^ (row & 3)) & 3) << 4);
                LDSM_X4(aH[mf], ad);
                LDSM_X4(aL[mf], ad + 8192);
            }
            #pragma unroll
            for (int g = 0; g < 2; g++) {
                int row = wn0 + g * 16 + (lane & 7) + ((lane >> 4) & 1) * 8;
                int ch = 2 * kh + ((lane >> 3) & 1);
                uint32_t ad = stage + 16384 + row * 64 + (((ch ^ (row & 3)) & 3) << 4);
                LDSM_X4(bHf[g], ad);
                LDSM_X4(bLf[g], ad + 8192);
            }
            #pragma unroll
            for (int mf = 0; mf < 4; mf++)
                #pragma unroll
                for (int g = 0; g < 2; g++)
                    #pragma unroll
                    for (int nh = 0; nh < 2; nh++) {
                        float* c = acc[mf][g * 2 + nh];
                        MMA16816(c, aH[mf], bHf[g][nh * 2], bHf[g][nh * 2 + 1]);
                        MMA16816(c, aH[mf], bLf[g][nh * 2], bLf[g][nh * 2 + 1]);
                        MMA16816(c, aL[mf], bHf[g][nh * 2], bHf[g][nh * 2 + 1]);
                    }
        }
        __syncthreads();
    }

    // epilogue: scatter to q/k hi/lo [bh][t][d] and v^T hi/lo [bh][d][t]
    const int mat = n0 / (HH * DH);     // tile never crosses a matrix boundary
    #pragma unroll
    for (int mf = 0; mf < 4; mf++) {
        int r0 = m0 + wm0 + mf * 16 + (lane >> 2);
        #pragma unroll
        for (int nf = 0; nf < 4; nf++) {
            float* a = acc[mf][nf];
            #pragma unroll
            for (int c2 = 0; c2 < 2; c2++) {
                int n = n0 + wn0 + nf * 8 + (lane & 3) * 2 + c2;
                int rem = n - mat * (HH * DH);
                int hh = rem >> 6, d = rem & 63;
                #pragma unroll
                for (int rr = 0; rr < 2; rr++) {
                    int r = r0 + rr * 8;
                    int b = r >> 11, t = r & 2047;
                    int bh = b * HH + hh;
                    float v = a[c2 + rr * 2];
                    __nv_bfloat16 hi, lo;
                    split_bf16(v, hi, lo);
                    if (mat == 0) {
                        size_t off = ((size_t)bh * TT + t) * DH + d;
                        gq_hi[off] = hi; gq_lo[off] = lo;
                    } else if (mat == 1) {
                        size_t off = ((size_t)bh * TT + t) * DH + d;
                        gk_hi[off] = hi; gk_lo[off] = lo;
                    } else {
                        size_t off = ((size_t)bh * DH + d) * TT + t;
                        gvT_hi[off] = hi; gvT_lo[off] = lo;
                    }
                }
            }
        }
    }
}

// ---------------- K4: scores via HMMA; bf16 att out + fused col expsums -----
#define SSMEM 65536
__global__ __launch_bounds__(256) void k_scores() {
    int zs = blockIdx.x, zt = blockIdx.y, bh = blockIdx.z;
    if (zs > zt) return;
    int s0 = zs * 128, t0 = zt * 128;
    extern __shared__ __align__(128) char smem[];
    const uint32_t sb = smem_u32(smem);
    const int tid = threadIdx.x;
    const int wid = tid >> 5, lane = tid & 31;
    const int wm0 = (wid & 1) * 64;
    const int wn0 = (wid >> 1) * 32;

    #pragma unroll
    for (int i = 0; i < 4; i++) {
        int j = tid + i * 256;                 // 0..1023
        int row = j >> 3, ch = j & 7;
        uint32_t soff = row * 128 + (((ch ^ (row & 7)) & 7) << 4);
        size_t gq = ((size_t)bh * TT + t0 + row) * 128 + ch * 16;
        size_t gk = ((size_t)bh * TT + s0 + row) * 128 + ch * 16;
        cpasync16(sb + soff,         (const char*)gq_hi + gq);
        cpasync16(sb + 16384 + soff, (const char*)gq_lo + gq);
        cpasync16(sb + 32768 + soff, (const char*)gk_hi + gk);
        cpasync16(sb + 49152 + soff, (const char*)gk_lo + gk);
    }
    CP_COMMIT();
    CP_WAIT0();
    __syncthreads();

    float acc[4][4][4];
    #pragma unroll
    for (int i = 0; i < 4; i++)
        #pragma unroll
        for (int j = 0; j < 4; j++)
            #pragma unroll
            for (int q = 0; q < 4; q++) acc[i][j][q] = 0.f;

    #pragma unroll
    for (int kh = 0; kh < 4; kh++) {
        uint32_t aH[4][4], aL[4][4], bHf[2][4], bLf[2][4];
        #pragma unroll
        for (int mf = 0; mf < 4; mf++) {
            int row = wm0 + mf * 16 + (lane & 7) + ((lane >> 3) & 1) * 8;
            int ch = 2 * kh + (lane >> 4);
            uint32_t ad = sb + row * 128 + (((ch ^ (row & 7)) & 7) << 4);
            LDSM_X4(aH[mf], ad);
            LDSM_X4(aL[mf], ad + 16384);
        }
        #pragma unroll
        for (int g = 0; g < 2; g++) {
            int row = wn0 + g * 16 + (lane & 7) + ((lane >> 4) & 1) * 8;
            int ch = 2 * kh + ((lane >> 3) & 1);
            uint32_t ad = sb + 32768 + row * 128 + (((ch ^ (row & 7)) & 7) << 4);
            LDSM_X4(bHf[g], ad);
            LDSM_X4(bLf[g], ad + 16384);
        }
        #pragma unroll
        for (int mf = 0; mf < 4; mf++)
            #pragma unroll
            for (int g = 0; g < 2; g++)
                #pragma unroll
                for (int nh = 0; nh < 2; nh++) {
                    float* c = acc[mf][g * 2 + nh];
                    MMA16816(c, aH[mf], bHf[g][nh * 2], bHf[g][nh * 2 + 1]);
                    MMA16816(c, aH[mf], bLf[g][nh * 2], bLf[g][nh * 2 + 1]);
                    MMA16816(c, aL[mf], bHf[g][nh * 2], bHf[g][nh * 2 + 1]);
                }
    }

    // epilogue: bf16 score store + masked per-column exp partial sums
    __nv_bfloat16* out = g_att + (size_t)bh * TT * TT;
    float csum[4][2];
    #pragma unroll
    for (int nf = 0; nf < 4; nf++) { csum[nf][0] = 0.f; csum[nf][1] = 0.f; }
    #pragma unroll
    for (int mf = 0; mf < 4; mf++) {
        int t = t0 + wm0 + mf * 16 + (lane >> 2);
        __nv_bfloat16* p0 = out + (size_t)t * TT;
        __nv_bfloat16* p1 = p0 + (size_t)8 * TT;
        #pragma unroll
        for (int nf = 0; nf < 4; nf++) {
            int s = s0 + wn0 + nf * 8 + (lane & 3) * 2;
            float* a = acc[mf][nf];
            float v0 = a[0] * 8.0f, v1 = a[1] * 8.0f;
            float v2 = a[2] * 8.0f, v3 = a[3] * 8.0f;
            *(__nv_bfloat162*)(p0 + s) = __floats2bfloat162_rn(v0, v1);
            *(__nv_bfloat162*)(p1 + s) = __floats2bfloat162_rn(v2, v3);
            csum[nf][0] += (s     <= t     ? __expf(v0) : 0.f)
                         + (s     <= t + 8 ? __expf(v2) : 0.f);
            csum[nf][1] += (s + 1 <= t     ? __expf(v1) : 0.f)
                         + (s + 1 <= t + 8 ? __expf(v3) : 0.f);
        }
    }
    #pragma unroll
    for (int nf = 0; nf < 4; nf++) {
        #pragma unroll
        for (int k = 0; k < 2; k++) {
            csum[nf][k] += __shfl_xor_sync(0xffffffffu, csum[nf][k], 4);
            csum[nf][k] += __shfl_xor_sync(0xffffffffu, csum[nf][k], 8);
            csum[nf][k] += __shfl_xor_sync(0xffffffffu, csum[nf][k], 16);
        }
    }
    if (lane < 4) {
        size_t base = (((size_t)bh * 16 + zt) * 2 + (wid & 1)) * TT;
        #pragma unroll
        for (int nf = 0; nf < 4; nf++) {
            int s = s0 + wn0 + nf * 8 + lane * 2;
            *(float2*)&g_cpart[base + s] = make_float2(csum[nf][0], csum[nf][1]);
        }
    }
}

// ---------------- K5: per-column softmax sums from partials ------------------
__global__ void k_colstats() {
    int bh = blockIdx.y;
    int s = blockIdx.x * 256 + threadIdx.x;
    int zs = s >> 7;
    float sum = 0.f;
    for (int zt = zs; zt < 16; zt++) {
        size_t base = (((size_t)bh * 16 + zt) * 2) * TT;
        sum += g_cpart[base + s] + g_cpart[base + TT + s];
    }
    g_cinv[bh * TT + s] = 1.0f / sum;
}

// ---------------- K6: o = softmax(att) @ v via HMMA -------------------------
#define ASMEM 49152
__global__ __launch_bounds__(256) void k_av() {
    int zt = blockIdx.x, bh = blockIdx.y;
    int t0 = zt * 128;
    int b = bh / HH, h = bh % HH;
    extern __shared__ __align__(128) char smem[];
    const uint32_t sb = smem_u32(smem);
    char* whi = smem;
    char* wlo = smem + 16384;
    const int tid = threadIdx.x;
    const int wid = tid >> 5, lane = tid & 31;
    const int wm0 = (wid & 3) * 32;
    const int wn0 = (wid >> 2) * 32;

    const __nv_bfloat16* att = g_att + (size_t)bh * TT * TT;
    const float* ci  = g_cinv + bh * TT;

    float acc[2][4][4];
    #pragma unroll
    for (int i = 0; i < 2; i++)
        #pragma unroll
        for (int j = 0; j < 4; j++)
            #pragma unroll
            for (int q = 0; q < 4; q++) acc[i][j][q] = 0.f;

    int nchunks = 2 * zt + 2;
    for (int c = 0; c < nchunks; c++) {
        int s0 = c * 64;
        #pragma unroll
        for (int i = 0; i < 2; i++) {
            int j = tid + i * 256;             // 0..511
            int row = j >> 3, ch = j & 7;
            uint32_t soff = row * 128 + (((ch ^ (row & 7)) & 7) << 4);
            size_t gv = ((size_t)bh * DH + row) * (TT * 2) + s0 * 2 + ch * 16;
            cpasync16(sb + 32768 + soff, (const char*)gvT_hi + gv);
            cpasync16(sb + 40960 + soff, (const char*)gvT_lo + gv);
        }
        CP_COMMIT();
        // w tile: 128 t-rows x 64 s processed as bf162 pairs
        #pragma unroll
        for (int i = 0; i < 16; i++) {
            int j = tid + i * 256;             // 0..4095 pairs
            int row = j >> 5, p = j & 31;
            int sc = p * 2;
            int t = t0 + row, s = s0 + sc;
            __nv_bfloat162 av = *(const __nv_bfloat162*)(att + (size_t)t * TT + s);
            float w0 = (s     <= t) ? __expf(__bfloat162float(av.x)) * ci[s]     : 0.f;
            float w1 = (s + 1 <= t) ? __expf(__bfloat162float(av.y)) * ci[s + 1] : 0.f;
            __nv_bfloat16 h0, l0, h1, l1;
            split_bf16(w0, h0, l0);
            split_bf16(w1, h1, l1);
            int ch = sc >> 3;
            uint32_t soff = row * 128 + (((ch ^ (row & 7)) & 7) << 4) + (sc & 7) * 2;
            *(__nv_bfloat162*)(whi + soff) = __halves2bfloat162(h0, h1);
            *(__nv_bfloat162*)(wlo + soff) = __halves2bfloat162(l0, l1);
        }
        CP_WAIT0();
        __syncthreads();

        #pragma unroll
        for (int kh = 0; kh < 4; kh++) {
            uint32_t aH[2][4], aL[2][4], bHf[2][4], bLf[2][4];
            #pragma unroll
            for (int mf = 0; mf < 2; mf++) {
                int row = wm0 + mf * 16 + (lane & 7) + ((lane >> 3) & 1) * 8;
                int ch = 2 * kh + (lane >> 4);
                uint32_t ad = sb + row * 128 + (((ch ^ (row & 7)) & 7) << 4);
                LDSM_X4(aH[mf], ad);
                LDSM_X4(aL[mf], ad + 16384);
            }
            #pragma unroll
            for (int g = 0; g < 2; g++) {
                int row = wn0 + g * 16 + (lane & 7) + ((lane >> 4) & 1) * 8;
                int ch = 2 * kh + ((lane >> 3) & 1);
                uint32_t ad = sb + 32768 + row * 128 + (((ch ^ (row & 7)) & 7) << 4);
                LDSM_X4(bHf[g], ad);
                LDSM_X4(bLf[g], ad + 8192);
            }
            #pragma unroll
            for (int mf = 0; mf < 2; mf++)
                #pragma unroll
                for (int g = 0; g < 2; g++)
                    #pragma unroll
                    for (int nh = 0; nh < 2; nh++) {
                        float* cc = acc[mf][g * 2 + nh];
                        MMA16816(cc, aH[mf], bHf[g][nh * 2], bHf[g][nh * 2 + 1]);
                        MMA16816(cc, aH[mf], bLf[g][nh * 2], bLf[g][nh * 2 + 1]);
                        MMA16816(cc, aL[mf], bHf[g][nh * 2], bHf[g][nh * 2 + 1]);
                    }
        }
        __syncthreads();
    }

    // epilogue: o -> gA fp16 (single store per pair)
    #pragma unroll
    for (int mf = 0; mf < 2; mf++) {
        int t = t0 + wm0 + mf * 16 + (lane >> 2);
        #pragma unroll
        for (int nf = 0; nf < 4; nf++) {
            int d = wn0 + nf * 8 + (lane & 3) * 2;
            float* a = acc[mf][nf];
            #pragma unroll
            for (int rr = 0; rr < 2; rr++) {
                int tt = t + rr * 8;
                size_t off = ((size_t)b * TT + tt) * EE + h * DH + d;
                *(__half2*)(gA_h + off) = __floats2half2_rn(a[rr * 2], a[rr * 2 + 1]);
            }
        }
    }
}

// ---------------- K7: logits GEMM (fp16 2-pass, 3-stage, 2 CTA/SM) ----------
// A = fp16(gA) single; W = fp16 hi/lo. logits = A*(Whi+Wlo): 2 mma passes.
#define GSTAGE 24576                 // A 8K, Bhi 8K, Blo 8K
#define GSMEM_BYTES (3 * GSTAGE)     // 72 KB
__global__ __launch_bounds__(256, 2) void k_gemm(const float* __restrict__ bias,
                                                 float* __restrict__ C) {
    extern __shared__ __align__(128) char smem[];
    const uint32_t sb = smem_u32(smem);
    const int tid = threadIdx.x;
    const int wid = tid >> 5, lane = tid & 31;
    const int m0 = blockIdx.x * 128;
    const int n0 = blockIdx.y * 128;
    const int wm0 = (wid & 1) * 64;
    const int wn0 = (wid >> 1) * 32;

    float acc[4][4][4];
    #pragma unroll
    for (int i = 0; i < 4; i++)
        #pragma unroll
        for (int j = 0; j < 4; j++)
            #pragma unroll
            for (int q = 0; q < 4; q++) acc[i][j][q] = 0.f;

    auto load_stage = [&](int p, int k0) {
        uint32_t base = sb + p * GSTAGE;
        int kbyte = k0 * 2;
        #pragma unroll
        for (int half = 0; half < 2; half++) {
            int j = tid + half * 256;
            int row = j >> 2, ch = j & 3;
            uint32_t soff = row * 64 + (((ch ^ (row & 3)) & 3) << 4);
            size_t ga = (size_t)(m0 + row) * (EE * 2) + kbyte + ch * 16;
            cpasync16(base + soff, (const char*)gA_h + ga);
            int nn = n0 + row; if (nn >= VV) nn = VV - 1;
            size_t gb = (size_t)nn * (EE * 2) + kbyte + ch * 16;
            cpasync16(base + 8192  + soff, (const char*)gWh_hi + gb);
            cpasync16(base + 16384 + soff, (const char*)gWh_lo + gb);
        }
    };

    load_stage(0, 0);
    CP_COMMIT();
    load_stage(1, 32);
    CP_COMMIT();

    const int NIT = EE / 32;    // 24
    int buf = 0;
    for (int it = 0; it < NIT; it++) {
        if (it + 1 < NIT) { CP_WAIT1(); } else { CP_WAIT0(); }
        __syncthreads();
        if (it + 2 < NIT) {
            int nb = buf + 2; if (nb >= 3) nb -= 3;
            load_stage(nb, (it + 2) * 32);
            CP_COMMIT();
        }
        uint32_t stage = sb + buf * GSTAGE;
        #pragma unroll
        for (int kh = 0; kh < 2; kh++) {
            uint32_t aH[4][4], bHf[2][4], bLf[2][4];
            #pragma unroll
            for (int mf = 0; mf < 4; mf++) {
                int row = wm0 + mf * 16 + (lane & 7) + ((lane >> 3) & 1) * 8;
                int ch = 2 * kh + (lane >> 4);
                uint32_t ad = stage + row * 64 + (((ch ^ (row & 3)) & 3) << 4);
                LDSM_X4(aH[mf], ad);
            }
            #pragma unroll
            for (int g = 0; g < 2; g++) {
                int row = wn0 + g * 16 + (lane & 7) + ((lane >> 4) & 1) * 8;
                int ch = 2 * kh + ((lane >> 3) & 1);
                uint32_t ad = stage + 8192 + row * 64 + (((ch ^ (row & 3)) & 3) << 4);
                LDSM_X4(bHf[g], ad);
                LDSM_X4(bLf[g], ad + 8192);
            }
            #pragma unroll
            for (int mf = 0; mf < 4; mf++)
                #pragma unroll
                for (int g = 0; g < 2; g++)
                    #pragma unroll
                    for (int nh = 0; nh < 2; nh++) {
                        float* c = acc[mf][g * 2 + nh];
                        MMAF16(c, aH[mf], bHf[g][nh * 2], bHf[g][nh * 2 + 1]);
                        MMAF16(c, aH[mf], bLf[g][nh * 2], bLf[g][nh * 2 + 1]);
                    }
        }
        buf++; if (buf == 3) buf = 0;
    }

    // epilogue: scalar logit stores (VV odd -> 4B-aligned rows) + expsum partials
    const int py = blockIdx.y * 4 + (wid >> 1);
    #pragma unroll
    for (int mf = 0; mf < 4; mf++) {
        int r = m0 + wm0 + mf * 16 + (lane >> 2);
        float* p0 = C + (size_t)r * VV;
        float* p1 = p0 + (size_t)8 * VV;
        float e0 = 0.f, e1 = 0.f;
        #pragma unroll
        for (int nf = 0; nf < 4; nf++) {
            int cc = n0 + wn0 + nf * 8 + (lane & 3) * 2;
            float* a = acc[mf][nf];
            if (cc < VV) {
                float bv = __ldg(&bias[cc]);
                float v0 = a[0] + bv, v2 = a[2] + bv;
                p0[cc] = v0; p1[cc] = v2;
                e0 += __expf(v0);
                e1 += __expf(v2);
            }
            if (cc + 1 < VV) {
                float bv = __ldg(&bias[cc + 1]);
                float v1 = a[1] + bv, v3 = a[3] + bv;
                p0[cc + 1] = v1; p1[cc + 1] = v3;
                e0 += __expf(v1);
                e1 += __expf(v3);
            }
        }
        e0 += __shfl_xor_sync(0xffffffffu, e0, 1);
        e0 += __shfl_xor_sync(0xffffffffu, e0, 2);
        e1 += __shfl_xor_sync(0xffffffffu, e1, 1);
        e1 += __shfl_xor_sync(0xffffffffu, e1, 2);
        if ((lane & 3) == 0) {
            g_part[(size_t)r * NPART + py]       = e0;
            g_part[(size_t)(r + 8) * NPART + py] = e1;
        }
    }
}

// ---------------- K8: per-row lse from partials + target gather -------------
__global__ __launch_bounds__(256) void k_rowloss(const float* __restrict__ logits,
                                                 const int* __restrict__ y) {
    int row = blockIdx.x;
    int tid = threadIdx.x;
    float s = 0.f;
    for (int i = tid; i < NPART; i += 256) s += g_part[(size_t)row * NPART + i];
    __shared__ float ss[256];
    ss[tid] = s;
    __syncthreads();
    for (int off = 128; off > 0; off >>= 1) {
        if (tid < off) ss[tid] += ss[tid + off];
        __syncthreads();
    }
    if (tid == 0) {
        g_rowloss[row] = logf(ss[0]) - logits[(size_t)row * VV + y[row]];
    }
}

// ---------------- K9: mean -> loss scalar -----------------------------------
__global__ void k_loss(float* __restrict__ out) {
    __shared__ float sb[256];
    int tid = threadIdx.x;
    float s = 0.f;
    for (int i = tid; i < NTOK; i += 256) s += g_rowloss[i];
    sb[tid] = s;
    __syncthreads();
    for (int off = 128; off > 0; off >>= 1) {
        if (tid < off) sb[tid] += sb[tid + off];
        __syncthreads();
    }
    if (tid == 0) out[0] = sb[0] / (float)NTOK;
}

// ---------------- launch -----------------------------------------------------
extern "C" void kernel_launch(void* const* d_in, const int* in_sizes, int n_in,
                              void* d_out, int out_size) {
    const int*   x    = (const int*)d_in[0];
    const int*   y    = (const int*)d_in[1];
    const float* tok  = (const float*)d_in[2];
    const float* pos  = (const float*)d_in[3];
    const float* Wq   = (const float*)d_in[4];
    const float* Wk   = (const float*)d_in[5];
    const float* Wv   = (const float*)d_in[6];
    const float* Wout = (const float*)d_in[7];
    const float* bout = (const float*)d_in[8];
    float* out = (float*)d_out;

    cudaFuncSetAttribute(k_projmma, cudaFuncAttributeMaxDynamicSharedMemorySize, PSMEM);
    cudaFuncSetAttribute(k_scores,  cudaFuncAttributeMaxDynamicSharedMemorySize, SSMEM);
    cudaFuncSetAttribute(k_av,      cudaFuncAttributeMaxDynamicSharedMemorySize, ASMEM);
    cudaFuncSetAttribute(k_gemm,    cudaFuncAttributeMaxDynamicSharedMemorySize, GSMEM_BYTES);

    k_embed<<<NTOK * EE / 256, 256>>>(x, tok, pos);
    k_packW<<<NQKV * EE / 256, 256>>>(Wq, Wk, Wv);
    k_cvtW<<<dim3((VV + 31) / 32, EE / 32), dim3(32, 8)>>>(Wout);

    k_projmma<<<dim3(NTOK / 128, NQKV / 128), 256, PSMEM>>>();

    k_scores<<<dim3(16, 16, BH), 256, SSMEM>>>();

    k_colstats<<<dim3(TT / 256, BH), 256>>>();

    k_av<<<dim3(TT / 128, BH), 256, ASMEM>>>();

    k_gemm<<<dim3(NTOK / 128, (VV + 127) / 128), 256, GSMEM_BYTES>>>(bout, out);

    k_rowloss<<<NTOK, 256>>>(out, y);

    long long nlogits = (long long)NTOK * VV;
    if ((long long)out_size > nlogits) {
        k_loss<<<1, 256>>>(out + nlogits);
    }
}